// round 10
// baseline (speedup 1.0000x reference)
#include <cuda_runtime.h>
#include <cuda_bf16.h>
#include <cuda_fp16.h>
#include <cstdint>

#define BB 8
#define NN 2048
#define CC 256
#define FF 128
#define MTOT (BB*NN)   // 16384

// ---------------- scratch (no cudaMalloc allowed) ----------------
__device__ __half        g_fx16[MTOT*FF];          // 4 MB
__device__ __half        g_gx16[MTOT*FF];          // 4 MB
__device__ float         g_hx [MTOT*FF];           // 8 MB
__device__ __half        g_hxT[(size_t)BB*FF*NN];  // [b][f][n] fp16 (scaled)
__device__ __half        g_eT[(size_t)BB*NN*NN];   // [b][m][n] fp16, 64 MB
__device__ float         g_spart[(size_t)BB*NN*16];// partial row sums
__device__ float         g_O [MTOT*FF];            // [b][f][m] 8 MB

#define HXT_SCALE 16384.0f
#define HXT_INV_SCALE (1.0f/16384.0f)

// ======================= PTX helpers =======================
__device__ __forceinline__ uint32_t smem_to_u32(const void* p) {
    uint32_t a;
    asm("{ .reg .u64 t; cvta.to.shared.u64 t, %1; cvt.u32.u64 %0, t; }" : "=r"(a) : "l"(p));
    return a;
}
#define CP_ASYNC16(dst, src) \
    asm volatile("cp.async.cg.shared.global [%0], [%1], 16;" :: "r"(dst), "l"(src) : "memory")
#define CP_COMMIT() asm volatile("cp.async.commit_group;" ::: "memory")
#define CP_WAIT(n)  asm volatile("cp.async.wait_group %0;" :: "n"(n) : "memory")

__device__ __forceinline__ void ldsm_x4(uint32_t& r0, uint32_t& r1, uint32_t& r2, uint32_t& r3, uint32_t a) {
    asm volatile("ldmatrix.sync.aligned.m8n8.x4.shared.b16 {%0,%1,%2,%3}, [%4];"
                 : "=r"(r0), "=r"(r1), "=r"(r2), "=r"(r3) : "r"(a));
}
__device__ __forceinline__ void ldsm_x2(uint32_t& r0, uint32_t& r1, uint32_t a) {
    asm volatile("ldmatrix.sync.aligned.m8n8.x2.shared.b16 {%0,%1}, [%2];"
                 : "=r"(r0), "=r"(r1) : "r"(a));
}
__device__ __forceinline__ void mma_f16(float c[4], const uint32_t a[4], const uint32_t b[2]) {
    asm volatile("mma.sync.aligned.m16n8k16.row.col.f32.f16.f16.f32 "
                 "{%0,%1,%2,%3}, {%4,%5,%6,%7}, {%8,%9}, {%0,%1,%2,%3};"
                 : "+f"(c[0]), "+f"(c[1]), "+f"(c[2]), "+f"(c[3])
                 : "r"(a[0]), "r"(a[1]), "r"(a[2]), "r"(a[3]), "r"(b[0]), "r"(b[1]));
}

// =================================================================
// proj_kernel: fused 3-way projection. 64-row tile.
//   fx, gx -> fp16 single; hx -> fp32
// =================================================================
__global__ __launch_bounds__(256) void proj_kernel(
    const float* __restrict__ x,
    const float* __restrict__ Wf, const float* __restrict__ bf,
    const float* __restrict__ Wg, const float* __restrict__ bg,
    const float* __restrict__ Wh, const float* __restrict__ bh)
{
    __shared__ float Xs[16][68];
    __shared__ float Wfs[16][128], Wgs[16][128], Whs[16][128];

    const int t  = threadIdx.x;
    const int tx = t & 15, ty = t >> 4;
    const int row0 = blockIdx.x * 64;

    float af[4][8], ag[4][8], ah[4][8];
    #pragma unroll
    for (int i = 0; i < 4; i++)
        #pragma unroll
        for (int j = 0; j < 8; j++) { af[i][j] = 0.f; ag[i][j] = 0.f; ah[i][j] = 0.f; }

    for (int k0 = 0; k0 < CC; k0 += 16) {
        {
            int r = t >> 2, cg = t & 3;
            float4 v = *(const float4*)&x[(size_t)(row0 + r) * CC + k0 + cg * 4];
            Xs[cg*4+0][r] = v.x; Xs[cg*4+1][r] = v.y;
            Xs[cg*4+2][r] = v.z; Xs[cg*4+3][r] = v.w;
        }
        #pragma unroll
        for (int e = t; e < 512; e += 256) {
            int k = e >> 5, cg = e & 31;
            *(float4*)&Wfs[k][cg*4] = *(const float4*)&Wf[(size_t)(k0 + k) * FF + cg * 4];
            *(float4*)&Wgs[k][cg*4] = *(const float4*)&Wg[(size_t)(k0 + k) * FF + cg * 4];
            *(float4*)&Whs[k][cg*4] = *(const float4*)&Wh[(size_t)(k0 + k) * FF + cg * 4];
        }
        __syncthreads();
        #pragma unroll
        for (int c = 0; c < 16; c++) {
            float4 av = *(const float4*)&Xs[c][ty*4];
            float a[4] = {av.x, av.y, av.z, av.w};
            float4 f0 = *(const float4*)&Wfs[c][tx*8];
            float4 f1 = *(const float4*)&Wfs[c][tx*8+4];
            float4 g0 = *(const float4*)&Wgs[c][tx*8];
            float4 g1 = *(const float4*)&Wgs[c][tx*8+4];
            float4 h0 = *(const float4*)&Whs[c][tx*8];
            float4 h1 = *(const float4*)&Whs[c][tx*8+4];
            float bfv[8] = {f0.x,f0.y,f0.z,f0.w,f1.x,f1.y,f1.z,f1.w};
            float bgv[8] = {g0.x,g0.y,g0.z,g0.w,g1.x,g1.y,g1.z,g1.w};
            float bhv[8] = {h0.x,h0.y,h0.z,h0.w,h1.x,h1.y,h1.z,h1.w};
            #pragma unroll
            for (int i = 0; i < 4; i++)
                #pragma unroll
                for (int j = 0; j < 8; j++) {
                    af[i][j] += a[i] * bfv[j];
                    ag[i][j] += a[i] * bgv[j];
                    ah[i][j] += a[i] * bhv[j];
                }
        }
        __syncthreads();
    }

    #pragma unroll
    for (int i = 0; i < 4; i++) {
        int r = row0 + ty*4 + i;
        __half f8[8], g8[8];
        float hv[8];
        #pragma unroll
        for (int j = 0; j < 8; j++) {
            f8[j] = __float2half(af[i][j] + bf[tx*8+j]);
            g8[j] = __float2half(ag[i][j] + bg[tx*8+j]);
            hv[j] = ah[i][j] + bh[tx*8+j];
        }
        size_t o = (size_t)r * FF + tx*8;
        *(uint4*)&g_fx16[o] = *(const uint4*)f8;
        *(uint4*)&g_gx16[o] = *(const uint4*)g8;
        *(float4*)&g_hx[o]     = make_float4(hv[0], hv[1], hv[2], hv[3]);
        *(float4*)&g_hx[o + 4] = make_float4(hv[4], hv[5], hv[6], hv[7]);
    }
}

// =================================================================
// score_mma: S tile = fx @ gx^T, single fp16 chain, 256 threads,
// 8 warps 64x32 tiles, both K-chunks prefetched, 2 CTAs/SM.
// epilogue: e=exp(S), transposed fp16 store, row sums.
// grid (jt=16, it=16, b=8).
// =================================================================
#define S2_A  0
#define S2_B  18432        // 128*72*2
#define S2_CH 36864
#define SC_SMEM (2*S2_CH + 512)

__global__ __launch_bounds__(256, 2) void score_mma()
{
    extern __shared__ char smem[];
    const uint32_t sb = smem_to_u32(smem);
    const int tid  = threadIdx.x;
    const int lane = tid & 31, wid = tid >> 5;
    const int wrow = wid >> 2, wcol = wid & 3;
    const int R0 = wrow * 64, C0 = wcol * 32;
    const int b = blockIdx.z, it = blockIdx.y, jt = blockIdx.x;
    const int row0 = it * 128, col0 = jt * 128;

    const __half* fx = g_fx16 + (size_t)(b*NN + row0) * FF;
    const __half* gx = g_gx16 + (size_t)(b*NN + col0) * FF;

    // issue both K-chunks up front (double buffer)
    #pragma unroll
    for (int c = 0; c < 2; c++) {
        uint32_t bufb = sb + c * S2_CH;
        #pragma unroll
        for (int e = tid; e < 1024; e += 256) {
            int r = e >> 3, s = e & 7;
            uint32_t d = bufb + (uint32_t)(r*144 + s*16);
            size_t go = (size_t)r * FF + c*64 + s*8;
            CP_ASYNC16(d + S2_A, fx + go);
            CP_ASYNC16(d + S2_B, gx + go);
        }
        CP_COMMIT();
    }

    float acc[4][4][4];
    #pragma unroll
    for (int mi = 0; mi < 4; mi++)
        #pragma unroll
        for (int ni = 0; ni < 4; ni++)
            #pragma unroll
            for (int q = 0; q < 4; q++) acc[mi][ni][q] = 0.f;

    const int arow  = R0 + (lane & 15);
    const int acolB = ((lane >> 4) << 3);
    const int l15   = lane & 15;
    const int brow  = C0 + (l15 & 7);
    const int bcolB = ((l15 >> 3) << 3);

    #pragma unroll
    for (int c = 0; c < 2; c++) {
        if (c == 0) { CP_WAIT(1); } else { CP_WAIT(0); }
        __syncthreads();
        uint32_t bufb = sb + (uint32_t)c * S2_CH;
        #pragma unroll
        for (int ks = 0; ks < 4; ks++) {
            const int k0 = ks * 16;
            uint32_t aH[4][4], bH[4][2];
            #pragma unroll
            for (int mi = 0; mi < 4; mi++) {
                uint32_t ad = bufb + S2_A + (uint32_t)(((arow + mi*16)*72 + k0 + acolB) * 2);
                ldsm_x4(aH[mi][0], aH[mi][1], aH[mi][2], aH[mi][3], ad);
            }
            #pragma unroll
            for (int ni = 0; ni < 4; ni++) {
                uint32_t bd = bufb + S2_B + (uint32_t)(((brow + ni*8)*72 + k0 + bcolB) * 2);
                ldsm_x2(bH[ni][0], bH[ni][1], bd);
            }
            #pragma unroll
            for (int mi = 0; mi < 4; mi++)
                #pragma unroll
                for (int ni = 0; ni < 4; ni++)
                    mma_f16(acc[mi][ni], aH[mi], bH[ni]);
        }
        __syncthreads();
    }

    // ---------- epilogue: exp, row sums, transposed fp16 store ----------
    float* red = (float*)(smem + 2*S2_CH);
    if (tid < 128) red[tid] = 0.f;
    __syncthreads();

    #pragma unroll
    for (int mi = 0; mi < 4; mi++) {
        float s0 = 0.f, s1 = 0.f;
        #pragma unroll
        for (int ni = 0; ni < 4; ni++) {
            acc[mi][ni][0] = __expf(acc[mi][ni][0]);
            acc[mi][ni][1] = __expf(acc[mi][ni][1]);
            acc[mi][ni][2] = __expf(acc[mi][ni][2]);
            acc[mi][ni][3] = __expf(acc[mi][ni][3]);
            s0 += acc[mi][ni][0] + acc[mi][ni][1];
            s1 += acc[mi][ni][2] + acc[mi][ni][3];
        }
        s0 += __shfl_xor_sync(0xffffffffu, s0, 1);
        s0 += __shfl_xor_sync(0xffffffffu, s0, 2);
        s1 += __shfl_xor_sync(0xffffffffu, s1, 1);
        s1 += __shfl_xor_sync(0xffffffffu, s1, 2);
        if ((lane & 3) == 0) {
            int r = R0 + mi*16 + (lane >> 2);
            atomicAdd(&red[r], s0);
            atomicAdd(&red[r + 8], s1);
        }
    }
    __syncthreads();
    if (tid < 128)
        g_spart[((size_t)(b*NN) + row0 + tid) * 16 + jt] = red[tid];

    // stage [j][i] (128 x 136 fp16), single pass
    __half* stage = (__half*)smem;
    #pragma unroll
    for (int mi = 0; mi < 4; mi++)
        #pragma unroll
        for (int ni = 0; ni < 4; ni++)
            #pragma unroll
            for (int q = 0; q < 4; q++) {
                int i = R0 + mi*16 + (lane >> 2) + ((q >> 1) << 3);
                int j = C0 + ni*8 + 2*(lane & 3) + (q & 1);
                stage[j*136 + i] = __float2half(acc[mi][ni][q]);
            }
    __syncthreads();
    {
        int j = tid >> 1, half = tid & 1;
        uint4* dst = (uint4*)(g_eT + ((size_t)(b*NN + col0 + j))*NN + row0 + half*64);
        const uint4* src = (const uint4*)(stage + j*136 + half*64);
        #pragma unroll
        for (int i = 0; i < 8; i++) dst[i] = src[i];
    }
}

// =================================================================
// hxT_kernel: hxT[b][f][n] = fp16( hx[b][n][f]/rowsum[n] * 2^14 )
// =================================================================
__global__ __launch_bounds__(256) void hxT_kernel()
{
    __shared__ __half stage[128][136];
    __shared__ float inv[128];
    const int b = blockIdx.y, n0 = blockIdx.x * 128, t = threadIdx.x;

    if (t < 128) {
        const float* p = &g_spart[((size_t)(b*NN) + n0 + t) * 16];
        float s = 0.f;
        #pragma unroll
        for (int i = 0; i < 16; i++) s += p[i];
        inv[t] = HXT_SCALE / s;
    }
    __syncthreads();

    const float* hx = g_hx + ((size_t)(b*NN + n0)) * FF;

    for (int e = t; e < 16384; e += 256) {
        int n = e >> 7, f = e & 127;
        stage[f][n] = __float2half(hx[e] * inv[n]);
    }
    __syncthreads();
    {
        int f = t >> 1, h = t & 1;
        uint4* dst = (uint4*)(g_hxT + ((size_t)(b*FF) + f) * NN + n0 + h*64);
        const uint4* src = (const uint4*)&stage[f][h*64];
        #pragma unroll
        for (int i = 0; i < 8; i++) dst[i] = src[i];
    }
}

// =================================================================
// out_mma: O[b][f][m] = (sum_n hxT[f][n]*eT[m][n]) * 2^-14
// CTA 128(f) x 64(m), K=2048 in 32 chunks, 3-stage cp.async, 2 CTAs/SM.
// single fp16 chain. grid (mt=32, b=8), 256 threads. (measured 44us)
// =================================================================
#define O_A  0             // 128*72*2 = 18432
#define O_B  18432         // 64*72*2 = 9216
#define O_CH 27648
#define OT_SMEM (3*O_CH)   // 82944

__global__ __launch_bounds__(256, 2) void out_mma()
{
    extern __shared__ char smem[];
    const uint32_t sb = smem_to_u32(smem);
    const int tid  = threadIdx.x;
    const int lane = tid & 31, wid = tid >> 5;
    const int wrow = wid >> 2, wcol = wid & 3;
    const int R0 = wrow * 64;       // f offset within 128
    const int C0 = wcol * 16;       // m offset within 64
    const int b = blockIdx.y, m0 = blockIdx.x * 64;

    const __half* Ah = g_hxT + (size_t)b * FF * NN;
    const __half* Bm = g_eT + (size_t)b * NN * NN + (size_t)m0 * NN;

    auto fill = [&](int buf, int kc) {
        uint32_t bufb = sb + (uint32_t)buf * O_CH;
        #pragma unroll
        for (int e = tid; e < 1024; e += 256) {
            int r = e >> 3, s = e & 7;
            size_t go = (size_t)r * NN + (size_t)kc*64 + s*8;
            CP_ASYNC16(bufb + O_A + (uint32_t)(r*144 + s*16), Ah + go);
        }
        #pragma unroll
        for (int e = tid; e < 512; e += 256) {
            int r = e >> 3, s = e & 7;
            size_t go = (size_t)r * NN + (size_t)kc*64 + s*8;
            CP_ASYNC16(bufb + O_B + (uint32_t)(r*144 + s*16), Bm + go);
        }
        CP_COMMIT();
    };

    float acc[4][2][4];
    #pragma unroll
    for (int mi = 0; mi < 4; mi++)
        #pragma unroll
        for (int ni = 0; ni < 2; ni++)
            #pragma unroll
            for (int q = 0; q < 4; q++) acc[mi][ni][q] = 0.f;

    fill(0, 0);
    fill(1, 1);
    fill(2, 2);

    const int arow  = R0 + (lane & 15);
    const int acolB = ((lane >> 4) << 3);
    const int bn    = C0 + ((lane >> 4) << 3) + (lane & 7);
    const int bk    = ((lane >> 3) & 1) << 3;

    for (int kc = 0; kc < 32; kc++) {
        if (kc == 31)      { CP_WAIT(0); }
        else if (kc == 30) { CP_WAIT(1); }
        else               { CP_WAIT(2); }
        __syncthreads();
        uint32_t bufb = sb + (uint32_t)(kc % 3) * O_CH;
        #pragma unroll
        for (int ks = 0; ks < 4; ks++) {
            const int k0 = ks * 16;
            uint32_t aH[4][4], bb[4];
            #pragma unroll
            for (int mi = 0; mi < 4; mi++) {
                uint32_t ad = bufb + O_A + (uint32_t)(((arow + mi*16)*72 + k0 + acolB) * 2);
                ldsm_x4(aH[mi][0], aH[mi][1], aH[mi][2], aH[mi][3], ad);
            }
            {
                uint32_t bd = bufb + O_B + (uint32_t)((bn*72 + k0 + bk) * 2);
                ldsm_x4(bb[0], bb[1], bb[2], bb[3], bd);
            }
            #pragma unroll
            for (int mi = 0; mi < 4; mi++) {
                mma_f16(acc[mi][0], aH[mi], &bb[0]);
                mma_f16(acc[mi][1], aH[mi], &bb[2]);
            }
        }
        __syncthreads();
        if (kc + 3 < 32) fill(kc % 3, kc + 3);
    }

    // epilogue: direct stores to g_O[b][f][m], scale 2^-14
    #pragma unroll
    for (int mi = 0; mi < 4; mi++)
        #pragma unroll
        for (int ni = 0; ni < 2; ni++) {
            int f = R0 + mi*16 + (lane >> 2);
            int m = m0 + C0 + ni*8 + 2*(lane & 3);
            float2 v0 = { acc[mi][ni][0]*HXT_INV_SCALE, acc[mi][ni][1]*HXT_INV_SCALE };
            float2 v1 = { acc[mi][ni][2]*HXT_INV_SCALE, acc[mi][ni][3]*HXT_INV_SCALE };
            *(float2*)&g_O[((size_t)(b*FF) + f    ) * NN + m] = v0;
            *(float2*)&g_O[((size_t)(b*FF) + f + 8) * NN + m] = v1;
        }
}

// =================================================================
// final_dense: out[16384x128] = g_O(flat) @ Wv + bv   (fp32 SIMT)
// =================================================================
__global__ __launch_bounds__(256) void final_dense(
    const float* __restrict__ W, const float* __restrict__ bias,
    float* __restrict__ out)
{
    const float* A = (const float*)g_O;

    __shared__ float Xs[16][68];
    __shared__ float Ws[16][128];

    const int t  = threadIdx.x;
    const int tx = t & 15, ty = t >> 4;
    const int row0 = blockIdx.x * 64;

    float acc[4][8];
    #pragma unroll
    for (int i = 0; i < 4; i++)
        #pragma unroll
        for (int j = 0; j < 8; j++) acc[i][j] = 0.f;

    for (int k0 = 0; k0 < FF; k0 += 16) {
        {
            int r = t >> 2, cg = t & 3;
            float4 v = *(const float4*)&A[(size_t)(row0 + r) * FF + k0 + cg * 4];
            Xs[cg*4+0][r] = v.x; Xs[cg*4+1][r] = v.y;
            Xs[cg*4+2][r] = v.z; Xs[cg*4+3][r] = v.w;
        }
        #pragma unroll
        for (int e = t; e < 512; e += 256) {
            int k = e >> 5, cg = e & 31;
            *(float4*)&Ws[k][cg*4] = *(const float4*)&W[(size_t)(k0 + k) * FF + cg * 4];
        }
        __syncthreads();
        #pragma unroll
        for (int c = 0; c < 16; c++) {
            float4 av = *(const float4*)&Xs[c][ty*4];
            float4 b0 = *(const float4*)&Ws[c][tx*8];
            float4 b1 = *(const float4*)&Ws[c][tx*8+4];
            float a[4] = {av.x, av.y, av.z, av.w};
            float bv[8] = {b0.x, b0.y, b0.z, b0.w, b1.x, b1.y, b1.z, b1.w};
            #pragma unroll
            for (int i = 0; i < 4; i++)
                #pragma unroll
                for (int j = 0; j < 8; j++)
                    acc[i][j] += a[i] * bv[j];
        }
        __syncthreads();
    }

    #pragma unroll
    for (int i = 0; i < 4; i++) {
        int r = row0 + ty*4 + i;
        float4 v0, v1;
        v0.x = acc[i][0] + bias[tx*8+0]; v0.y = acc[i][1] + bias[tx*8+1];
        v0.z = acc[i][2] + bias[tx*8+2]; v0.w = acc[i][3] + bias[tx*8+3];
        v1.x = acc[i][4] + bias[tx*8+4]; v1.y = acc[i][5] + bias[tx*8+5];
        v1.z = acc[i][6] + bias[tx*8+6]; v1.w = acc[i][7] + bias[tx*8+7];
        *(float4*)&out[(size_t)r * FF + tx*8]     = v0;
        *(float4*)&out[(size_t)r * FF + tx*8 + 4] = v1;
    }
}

// =================================================================
extern "C" void kernel_launch(void* const* d_in, const int* in_sizes, int n_in,
                              void* d_out, int out_size)
{
    const float* x  = (const float*)d_in[0];
    const float* Wf = (const float*)d_in[1];
    const float* bf = (const float*)d_in[2];
    const float* Wg = (const float*)d_in[3];
    const float* bg = (const float*)d_in[4];
    const float* Wh = (const float*)d_in[5];
    const float* bh = (const float*)d_in[6];
    const float* Wv = (const float*)d_in[7];
    const float* bv = (const float*)d_in[8];
    float* out = (float*)d_out;

    cudaFuncSetAttribute(score_mma, cudaFuncAttributeMaxDynamicSharedMemorySize, SC_SMEM);
    cudaFuncSetAttribute(out_mma,   cudaFuncAttributeMaxDynamicSharedMemorySize, OT_SMEM);

    // fused projections: fx/gx -> fp16, hx -> fp32
    proj_kernel<<<MTOT/64, 256>>>(x, Wf, bf, Wg, bg, Wh, bh);

    // scores + exp + transposed fp16 store + partial row sums
    score_mma<<<dim3(16, 16, 8), 256, SC_SMEM>>>();

    // hxT = hx / rowsum * 2^14, transposed, fp16
    hxT_kernel<<<dim3(16, 8), 256>>>();

    // O = hxT @ eT^T * 2^-14
    out_mma<<<dim3(32, 8), 256, OT_SMEM>>>();

    // final: reshape([B,F,N] flat as [B,N,F]) @ Wv + bv
    final_dense<<<MTOT/64, 256>>>(Wv, bv, out);
}

// round 11
// speedup vs baseline: 1.5257x; 1.5257x over previous
#include <cuda_runtime.h>
#include <cuda_bf16.h>
#include <cuda_fp16.h>
#include <cstdint>

#define BB 8
#define NN 2048
#define CC 256
#define FF 128
#define MTOT (BB*NN)   // 16384

// ---------------- scratch (no cudaMalloc allowed) ----------------
__device__ __half        g_fx16[MTOT*FF];          // 4 MB
__device__ __half        g_gx16[MTOT*FF];          // 4 MB
__device__ float         g_hx [MTOT*FF];           // 8 MB
__device__ __half        g_hxT[(size_t)BB*FF*NN];  // [b][f][n] fp16 (scaled)
__device__ __half        g_eT[(size_t)BB*NN*NN];   // [b][m][n] fp16, 64 MB
__device__ float         g_spart[(size_t)BB*NN*16];// partial row sums
__device__ float         g_O [MTOT*FF];            // [b][f][m] 8 MB

#define HXT_SCALE 16384.0f
#define HXT_INV_SCALE (1.0f/16384.0f)

// ======================= PTX helpers =======================
__device__ __forceinline__ uint32_t smem_to_u32(const void* p) {
    uint32_t a;
    asm("{ .reg .u64 t; cvta.to.shared.u64 t, %1; cvt.u32.u64 %0, t; }" : "=r"(a) : "l"(p));
    return a;
}
#define CP_ASYNC16(dst, src) \
    asm volatile("cp.async.cg.shared.global [%0], [%1], 16;" :: "r"(dst), "l"(src) : "memory")
#define CP_COMMIT() asm volatile("cp.async.commit_group;" ::: "memory")
#define CP_WAIT(n)  asm volatile("cp.async.wait_group %0;" :: "n"(n) : "memory")

__device__ __forceinline__ void ldsm_x4(uint32_t& r0, uint32_t& r1, uint32_t& r2, uint32_t& r3, uint32_t a) {
    asm volatile("ldmatrix.sync.aligned.m8n8.x4.shared.b16 {%0,%1,%2,%3}, [%4];"
                 : "=r"(r0), "=r"(r1), "=r"(r2), "=r"(r3) : "r"(a));
}
__device__ __forceinline__ void ldsm_x2(uint32_t& r0, uint32_t& r1, uint32_t a) {
    asm volatile("ldmatrix.sync.aligned.m8n8.x2.shared.b16 {%0,%1}, [%2];"
                 : "=r"(r0), "=r"(r1) : "r"(a));
}
__device__ __forceinline__ void mma_f16(float c[4], const uint32_t a[4], const uint32_t b[2]) {
    asm volatile("mma.sync.aligned.m16n8k16.row.col.f32.f16.f16.f32 "
                 "{%0,%1,%2,%3}, {%4,%5,%6,%7}, {%8,%9}, {%0,%1,%2,%3};"
                 : "+f"(c[0]), "+f"(c[1]), "+f"(c[2]), "+f"(c[3])
                 : "r"(a[0]), "r"(a[1]), "r"(a[2]), "r"(a[3]), "r"(b[0]), "r"(b[1]));
}

// =================================================================
// proj_kernel: fused 3-way projection. 64-row tile.
//   fx, gx -> fp16 single; hx -> fp32
// =================================================================
__global__ __launch_bounds__(256) void proj_kernel(
    const float* __restrict__ x,
    const float* __restrict__ Wf, const float* __restrict__ bf,
    const float* __restrict__ Wg, const float* __restrict__ bg,
    const float* __restrict__ Wh, const float* __restrict__ bh)
{
    __shared__ float Xs[16][68];
    __shared__ float Wfs[16][128], Wgs[16][128], Whs[16][128];

    const int t  = threadIdx.x;
    const int tx = t & 15, ty = t >> 4;
    const int row0 = blockIdx.x * 64;

    float af[4][8], ag[4][8], ah[4][8];
    #pragma unroll
    for (int i = 0; i < 4; i++)
        #pragma unroll
        for (int j = 0; j < 8; j++) { af[i][j] = 0.f; ag[i][j] = 0.f; ah[i][j] = 0.f; }

    for (int k0 = 0; k0 < CC; k0 += 16) {
        {
            int r = t >> 2, cg = t & 3;
            float4 v = *(const float4*)&x[(size_t)(row0 + r) * CC + k0 + cg * 4];
            Xs[cg*4+0][r] = v.x; Xs[cg*4+1][r] = v.y;
            Xs[cg*4+2][r] = v.z; Xs[cg*4+3][r] = v.w;
        }
        #pragma unroll
        for (int e = t; e < 512; e += 256) {
            int k = e >> 5, cg = e & 31;
            *(float4*)&Wfs[k][cg*4] = *(const float4*)&Wf[(size_t)(k0 + k) * FF + cg * 4];
            *(float4*)&Wgs[k][cg*4] = *(const float4*)&Wg[(size_t)(k0 + k) * FF + cg * 4];
            *(float4*)&Whs[k][cg*4] = *(const float4*)&Wh[(size_t)(k0 + k) * FF + cg * 4];
        }
        __syncthreads();
        #pragma unroll
        for (int c = 0; c < 16; c++) {
            float4 av = *(const float4*)&Xs[c][ty*4];
            float a[4] = {av.x, av.y, av.z, av.w};
            float4 f0 = *(const float4*)&Wfs[c][tx*8];
            float4 f1 = *(const float4*)&Wfs[c][tx*8+4];
            float4 g0 = *(const float4*)&Wgs[c][tx*8];
            float4 g1 = *(const float4*)&Wgs[c][tx*8+4];
            float4 h0 = *(const float4*)&Whs[c][tx*8];
            float4 h1 = *(const float4*)&Whs[c][tx*8+4];
            float bfv[8] = {f0.x,f0.y,f0.z,f0.w,f1.x,f1.y,f1.z,f1.w};
            float bgv[8] = {g0.x,g0.y,g0.z,g0.w,g1.x,g1.y,g1.z,g1.w};
            float bhv[8] = {h0.x,h0.y,h0.z,h0.w,h1.x,h1.y,h1.z,h1.w};
            #pragma unroll
            for (int i = 0; i < 4; i++)
                #pragma unroll
                for (int j = 0; j < 8; j++) {
                    af[i][j] += a[i] * bfv[j];
                    ag[i][j] += a[i] * bgv[j];
                    ah[i][j] += a[i] * bhv[j];
                }
        }
        __syncthreads();
    }

    #pragma unroll
    for (int i = 0; i < 4; i++) {
        int r = row0 + ty*4 + i;
        __half f8[8], g8[8];
        float hv[8];
        #pragma unroll
        for (int j = 0; j < 8; j++) {
            f8[j] = __float2half(af[i][j] + bf[tx*8+j]);
            g8[j] = __float2half(ag[i][j] + bg[tx*8+j]);
            hv[j] = ah[i][j] + bh[tx*8+j];
        }
        size_t o = (size_t)r * FF + tx*8;
        *(uint4*)&g_fx16[o] = *(const uint4*)f8;
        *(uint4*)&g_gx16[o] = *(const uint4*)g8;
        *(float4*)&g_hx[o]     = make_float4(hv[0], hv[1], hv[2], hv[3]);
        *(float4*)&g_hx[o + 4] = make_float4(hv[4], hv[5], hv[6], hv[7]);
    }
}

// =================================================================
// score_mma: S tile = fx @ gx^T, single fp16 chain, 256 threads,
// 8 warps 64x32 tiles, both K-chunks prefetched (double buffer).
// NO occupancy cap (reg spill avoidance). grid (jt=16, it=16, b=8).
// epilogue: e=exp(S), transposed fp16 store, row sums.
// =================================================================
#define S2_A  0
#define S2_B  18432        // 128*72*2
#define S2_CH 36864
#define SC_SMEM (2*S2_CH + 512)

__global__ __launch_bounds__(256, 1) void score_mma()
{
    extern __shared__ char smem[];
    const uint32_t sb = smem_to_u32(smem);
    const int tid  = threadIdx.x;
    const int lane = tid & 31, wid = tid >> 5;
    const int wrow = wid >> 2, wcol = wid & 3;
    const int R0 = wrow * 64, C0 = wcol * 32;
    const int b = blockIdx.z, it = blockIdx.y, jt = blockIdx.x;
    const int row0 = it * 128, col0 = jt * 128;

    const __half* fx = g_fx16 + (size_t)(b*NN + row0) * FF;
    const __half* gx = g_gx16 + (size_t)(b*NN + col0) * FF;

    // issue both K-chunks up front (double buffer)
    #pragma unroll
    for (int c = 0; c < 2; c++) {
        uint32_t bufb = sb + c * S2_CH;
        #pragma unroll
        for (int e = tid; e < 1024; e += 256) {
            int r = e >> 3, s = e & 7;
            uint32_t d = bufb + (uint32_t)(r*144 + s*16);
            size_t go = (size_t)r * FF + c*64 + s*8;
            CP_ASYNC16(d + S2_A, fx + go);
            CP_ASYNC16(d + S2_B, gx + go);
        }
        CP_COMMIT();
    }

    float acc[4][4][4];
    #pragma unroll
    for (int mi = 0; mi < 4; mi++)
        #pragma unroll
        for (int ni = 0; ni < 4; ni++)
            #pragma unroll
            for (int q = 0; q < 4; q++) acc[mi][ni][q] = 0.f;

    const int arow  = R0 + (lane & 15);
    const int acolB = ((lane >> 4) << 3);
    const int l15   = lane & 15;
    const int brow  = C0 + (l15 & 7);
    const int bcolB = ((l15 >> 3) << 3);

    #pragma unroll
    for (int c = 0; c < 2; c++) {
        if (c == 0) { CP_WAIT(1); } else { CP_WAIT(0); }
        __syncthreads();
        uint32_t bufb = sb + (uint32_t)c * S2_CH;
        #pragma unroll
        for (int ks = 0; ks < 4; ks++) {
            const int k0 = ks * 16;
            uint32_t aH[4][4], bH[4][2];
            #pragma unroll
            for (int mi = 0; mi < 4; mi++) {
                uint32_t ad = bufb + S2_A + (uint32_t)(((arow + mi*16)*72 + k0 + acolB) * 2);
                ldsm_x4(aH[mi][0], aH[mi][1], aH[mi][2], aH[mi][3], ad);
            }
            #pragma unroll
            for (int ni = 0; ni < 4; ni++) {
                uint32_t bd = bufb + S2_B + (uint32_t)(((brow + ni*8)*72 + k0 + bcolB) * 2);
                ldsm_x2(bH[ni][0], bH[ni][1], bd);
            }
            #pragma unroll
            for (int mi = 0; mi < 4; mi++)
                #pragma unroll
                for (int ni = 0; ni < 4; ni++)
                    mma_f16(acc[mi][ni], aH[mi], bH[ni]);
        }
        __syncthreads();
    }

    // ---------- epilogue: exp, row sums, transposed fp16 store ----------
    float* red = (float*)(smem + 2*S2_CH);
    if (tid < 128) red[tid] = 0.f;
    __syncthreads();

    #pragma unroll
    for (int mi = 0; mi < 4; mi++) {
        float s0 = 0.f, s1 = 0.f;
        #pragma unroll
        for (int ni = 0; ni < 4; ni++) {
            acc[mi][ni][0] = __expf(acc[mi][ni][0]);
            acc[mi][ni][1] = __expf(acc[mi][ni][1]);
            acc[mi][ni][2] = __expf(acc[mi][ni][2]);
            acc[mi][ni][3] = __expf(acc[mi][ni][3]);
            s0 += acc[mi][ni][0] + acc[mi][ni][1];
            s1 += acc[mi][ni][2] + acc[mi][ni][3];
        }
        s0 += __shfl_xor_sync(0xffffffffu, s0, 1);
        s0 += __shfl_xor_sync(0xffffffffu, s0, 2);
        s1 += __shfl_xor_sync(0xffffffffu, s1, 1);
        s1 += __shfl_xor_sync(0xffffffffu, s1, 2);
        if ((lane & 3) == 0) {
            int r = R0 + mi*16 + (lane >> 2);
            atomicAdd(&red[r], s0);
            atomicAdd(&red[r + 8], s1);
        }
    }
    __syncthreads();
    if (tid < 128)
        g_spart[((size_t)(b*NN) + row0 + tid) * 16 + jt] = red[tid];

    // stage [j][i] (128 x 136 fp16), single pass
    __half* stage = (__half*)smem;
    #pragma unroll
    for (int mi = 0; mi < 4; mi++)
        #pragma unroll
        for (int ni = 0; ni < 4; ni++)
            #pragma unroll
            for (int q = 0; q < 4; q++) {
                int i = R0 + mi*16 + (lane >> 2) + ((q >> 1) << 3);
                int j = C0 + ni*8 + 2*(lane & 3) + (q & 1);
                stage[j*136 + i] = __float2half(acc[mi][ni][q]);
            }
    __syncthreads();
    {
        int j = tid >> 1, half = tid & 1;
        uint4* dst = (uint4*)(g_eT + ((size_t)(b*NN + col0 + j))*NN + row0 + half*64);
        const uint4* src = (const uint4*)(stage + j*136 + half*64);
        #pragma unroll
        for (int i = 0; i < 8; i++) dst[i] = src[i];
    }
}

// =================================================================
// hxT_kernel: hxT[b][f][n] = fp16( hx[b][n][f]/rowsum[n] * 2^14 )
// =================================================================
__global__ __launch_bounds__(256) void hxT_kernel()
{
    __shared__ __half stage[128][136];
    __shared__ float inv[128];
    const int b = blockIdx.y, n0 = blockIdx.x * 128, t = threadIdx.x;

    if (t < 128) {
        const float* p = &g_spart[((size_t)(b*NN) + n0 + t) * 16];
        float s = 0.f;
        #pragma unroll
        for (int i = 0; i < 16; i++) s += p[i];
        inv[t] = HXT_SCALE / s;
    }
    __syncthreads();

    const float* hx = g_hx + ((size_t)(b*NN + n0)) * FF;

    for (int e = t; e < 16384; e += 256) {
        int n = e >> 7, f = e & 127;
        stage[f][n] = __float2half(hx[e] * inv[n]);
    }
    __syncthreads();
    {
        int f = t >> 1, h = t & 1;
        uint4* dst = (uint4*)(g_hxT + ((size_t)(b*FF) + f) * NN + n0 + h*64);
        const uint4* src = (const uint4*)&stage[f][h*64];
        #pragma unroll
        for (int i = 0; i < 8; i++) dst[i] = src[i];
    }
}

// =================================================================
// out_mma: O[b][f][m] = (sum_n hxT[f][n]*eT[m][n]) * 2^-14
// CTA 128(f) x 64(m), K=2048 in 32 chunks, 3-stage cp.async, 2 CTAs/SM.
// single fp16 chain. grid (mt=32, b=8), 256 threads.
// =================================================================
#define O_A  0             // 128*72*2 = 18432
#define O_B  18432         // 64*72*2 = 9216
#define O_CH 27648
#define OT_SMEM (3*O_CH)   // 82944

__global__ __launch_bounds__(256, 2) void out_mma()
{
    extern __shared__ char smem[];
    const uint32_t sb = smem_to_u32(smem);
    const int tid  = threadIdx.x;
    const int lane = tid & 31, wid = tid >> 5;
    const int wrow = wid >> 2, wcol = wid & 3;
    const int R0 = wrow * 64;       // f offset within 128
    const int C0 = wcol * 16;       // m offset within 64
    const int b = blockIdx.y, m0 = blockIdx.x * 64;

    const __half* Ah = g_hxT + (size_t)b * FF * NN;
    const __half* Bm = g_eT + (size_t)b * NN * NN + (size_t)m0 * NN;

    auto fill = [&](int buf, int kc) {
        uint32_t bufb = sb + (uint32_t)buf * O_CH;
        #pragma unroll
        for (int e = tid; e < 1024; e += 256) {
            int r = e >> 3, s = e & 7;
            size_t go = (size_t)r * NN + (size_t)kc*64 + s*8;
            CP_ASYNC16(bufb + O_A + (uint32_t)(r*144 + s*16), Ah + go);
        }
        #pragma unroll
        for (int e = tid; e < 512; e += 256) {
            int r = e >> 3, s = e & 7;
            size_t go = (size_t)r * NN + (size_t)kc*64 + s*8;
            CP_ASYNC16(bufb + O_B + (uint32_t)(r*144 + s*16), Bm + go);
        }
        CP_COMMIT();
    };

    float acc[4][2][4];
    #pragma unroll
    for (int mi = 0; mi < 4; mi++)
        #pragma unroll
        for (int ni = 0; ni < 2; ni++)
            #pragma unroll
            for (int q = 0; q < 4; q++) acc[mi][ni][q] = 0.f;

    fill(0, 0);
    fill(1, 1);
    fill(2, 2);

    const int arow  = R0 + (lane & 15);
    const int acolB = ((lane >> 4) << 3);
    const int bn    = C0 + ((lane >> 4) << 3) + (lane & 7);
    const int bk    = ((lane >> 3) & 1) << 3;

    for (int kc = 0; kc < 32; kc++) {
        if (kc == 31)      { CP_WAIT(0); }
        else if (kc == 30) { CP_WAIT(1); }
        else               { CP_WAIT(2); }
        __syncthreads();
        uint32_t bufb = sb + (uint32_t)(kc % 3) * O_CH;
        #pragma unroll
        for (int ks = 0; ks < 4; ks++) {
            const int k0 = ks * 16;
            uint32_t aH[4][4], bb[4];
            #pragma unroll
            for (int mi = 0; mi < 4; mi++) {
                uint32_t ad = bufb + O_A + (uint32_t)(((arow + mi*16)*72 + k0 + acolB) * 2);
                ldsm_x4(aH[mi][0], aH[mi][1], aH[mi][2], aH[mi][3], ad);
            }
            {
                uint32_t bd = bufb + O_B + (uint32_t)((bn*72 + k0 + bk) * 2);
                ldsm_x4(bb[0], bb[1], bb[2], bb[3], bd);
            }
            #pragma unroll
            for (int mi = 0; mi < 4; mi++) {
                mma_f16(acc[mi][0], aH[mi], &bb[0]);
                mma_f16(acc[mi][1], aH[mi], &bb[2]);
            }
        }
        __syncthreads();
        if (kc + 3 < 32) fill(kc % 3, kc + 3);
    }

    // epilogue: direct stores to g_O[b][f][m], scale 2^-14
    #pragma unroll
    for (int mi = 0; mi < 4; mi++)
        #pragma unroll
        for (int ni = 0; ni < 2; ni++) {
            int f = R0 + mi*16 + (lane >> 2);
            int m = m0 + C0 + ni*8 + 2*(lane & 3);
            float2 v0 = { acc[mi][ni][0]*HXT_INV_SCALE, acc[mi][ni][1]*HXT_INV_SCALE };
            float2 v1 = { acc[mi][ni][2]*HXT_INV_SCALE, acc[mi][ni][3]*HXT_INV_SCALE };
            *(float2*)&g_O[((size_t)(b*FF) + f    ) * NN + m] = v0;
            *(float2*)&g_O[((size_t)(b*FF) + f + 8) * NN + m] = v1;
        }
}

// =================================================================
// final_dense: out[16384x128] = g_O(flat) @ Wv + bv   (fp32 SIMT)
// =================================================================
__global__ __launch_bounds__(256) void final_dense(
    const float* __restrict__ W, const float* __restrict__ bias,
    float* __restrict__ out)
{
    const float* A = (const float*)g_O;

    __shared__ float Xs[16][68];
    __shared__ float Ws[16][128];

    const int t  = threadIdx.x;
    const int tx = t & 15, ty = t >> 4;
    const int row0 = blockIdx.x * 64;

    float acc[4][8];
    #pragma unroll
    for (int i = 0; i < 4; i++)
        #pragma unroll
        for (int j = 0; j < 8; j++) acc[i][j] = 0.f;

    for (int k0 = 0; k0 < FF; k0 += 16) {
        {
            int r = t >> 2, cg = t & 3;
            float4 v = *(const float4*)&A[(size_t)(row0 + r) * FF + k0 + cg * 4];
            Xs[cg*4+0][r] = v.x; Xs[cg*4+1][r] = v.y;
            Xs[cg*4+2][r] = v.z; Xs[cg*4+3][r] = v.w;
        }
        #pragma unroll
        for (int e = t; e < 512; e += 256) {
            int k = e >> 5, cg = e & 31;
            *(float4*)&Ws[k][cg*4] = *(const float4*)&W[(size_t)(k0 + k) * FF + cg * 4];
        }
        __syncthreads();
        #pragma unroll
        for (int c = 0; c < 16; c++) {
            float4 av = *(const float4*)&Xs[c][ty*4];
            float4 b0 = *(const float4*)&Ws[c][tx*8];
            float4 b1 = *(const float4*)&Ws[c][tx*8+4];
            float a[4] = {av.x, av.y, av.z, av.w};
            float bv[8] = {b0.x, b0.y, b0.z, b0.w, b1.x, b1.y, b1.z, b1.w};
            #pragma unroll
            for (int i = 0; i < 4; i++)
                #pragma unroll
                for (int j = 0; j < 8; j++)
                    acc[i][j] += a[i] * bv[j];
        }
        __syncthreads();
    }

    #pragma unroll
    for (int i = 0; i < 4; i++) {
        int r = row0 + ty*4 + i;
        float4 v0, v1;
        v0.x = acc[i][0] + bias[tx*8+0]; v0.y = acc[i][1] + bias[tx*8+1];
        v0.z = acc[i][2] + bias[tx*8+2]; v0.w = acc[i][3] + bias[tx*8+3];
        v1.x = acc[i][4] + bias[tx*8+4]; v1.y = acc[i][5] + bias[tx*8+5];
        v1.z = acc[i][6] + bias[tx*8+6]; v1.w = acc[i][7] + bias[tx*8+7];
        *(float4*)&out[(size_t)r * FF + tx*8]     = v0;
        *(float4*)&out[(size_t)r * FF + tx*8 + 4] = v1;
    }
}

// =================================================================
extern "C" void kernel_launch(void* const* d_in, const int* in_sizes, int n_in,
                              void* d_out, int out_size)
{
    const float* x  = (const float*)d_in[0];
    const float* Wf = (const float*)d_in[1];
    const float* bf = (const float*)d_in[2];
    const float* Wg = (const float*)d_in[3];
    const float* bg = (const float*)d_in[4];
    const float* Wh = (const float*)d_in[5];
    const float* bh = (const float*)d_in[6];
    const float* Wv = (const float*)d_in[7];
    const float* bv = (const float*)d_in[8];
    float* out = (float*)d_out;

    cudaFuncSetAttribute(score_mma, cudaFuncAttributeMaxDynamicSharedMemorySize, SC_SMEM);
    cudaFuncSetAttribute(out_mma,   cudaFuncAttributeMaxDynamicSharedMemorySize, OT_SMEM);

    // fused projections: fx/gx -> fp16, hx -> fp32
    proj_kernel<<<MTOT/64, 256>>>(x, Wf, bf, Wg, bg, Wh, bh);

    // scores + exp + transposed fp16 store + partial row sums
    score_mma<<<dim3(16, 16, 8), 256, SC_SMEM>>>();

    // hxT = hx / rowsum * 2^14, transposed, fp16
    hxT_kernel<<<dim3(16, 8), 256>>>();

    // O = hxT @ eT^T * 2^-14
    out_mma<<<dim3(32, 8), 256, OT_SMEM>>>();

    // final: reshape([B,F,N] flat as [B,N,F]) @ Wv + bv
    final_dense<<<MTOT/64, 256>>>(Wv, bv, out);
}

// round 13
// speedup vs baseline: 2.6182x; 1.7161x over previous
#include <cuda_runtime.h>
#include <cuda_bf16.h>
#include <cuda_fp16.h>
#include <cstdint>

#define BB 8
#define NN 2048
#define CC 256
#define FF 128
#define MTOT (BB*NN)   // 16384

// ---------------- scratch (no cudaMalloc allowed) ----------------
__device__ __half        g_fx16[MTOT*FF];          // 4 MB
__device__ __half        g_gx16[MTOT*FF];          // 4 MB
__device__ float         g_hx [MTOT*FF];           // 8 MB
__device__ __half        g_hxT[(size_t)BB*FF*NN];  // [b][f][n] fp16 (scaled)
__device__ __half        g_eT[(size_t)BB*NN*NN];   // [b][m][n] fp16, 64 MB
__device__ float         g_spart[(size_t)BB*NN*16];// partial row sums
__device__ float         g_O [MTOT*FF];            // [b][f][m] 8 MB
__device__ __half        g_Wt[3*FF*CC];            // Wf/Wg/Wh transposed fp16 [o][col][k]
__device__ __half        g_Wvt[FF*FF];             // Wv transposed fp16 [col][k]

#define HXT_SCALE 16384.0f
#define HXT_INV_SCALE (1.0f/16384.0f)

// ======================= PTX helpers =======================
__device__ __forceinline__ uint32_t smem_to_u32(const void* p) {
    uint32_t a;
    asm("{ .reg .u64 t; cvta.to.shared.u64 t, %1; cvt.u32.u64 %0, t; }" : "=r"(a) : "l"(p));
    return a;
}
#define CP_ASYNC16(dst, src) \
    asm volatile("cp.async.cg.shared.global [%0], [%1], 16;" :: "r"(dst), "l"(src) : "memory")
#define CP_COMMIT() asm volatile("cp.async.commit_group;" ::: "memory")
#define CP_WAIT(n)  asm volatile("cp.async.wait_group %0;" :: "n"(n) : "memory")

__device__ __forceinline__ void ldsm_x4(uint32_t& r0, uint32_t& r1, uint32_t& r2, uint32_t& r3, uint32_t a) {
    asm volatile("ldmatrix.sync.aligned.m8n8.x4.shared.b16 {%0,%1,%2,%3}, [%4];"
                 : "=r"(r0), "=r"(r1), "=r"(r2), "=r"(r3) : "r"(a));
}
__device__ __forceinline__ void ldsm_x2(uint32_t& r0, uint32_t& r1, uint32_t a) {
    asm volatile("ldmatrix.sync.aligned.m8n8.x2.shared.b16 {%0,%1}, [%2];"
                 : "=r"(r0), "=r"(r1) : "r"(a));
}
__device__ __forceinline__ void mma_f16(float c[4], const uint32_t a[4], const uint32_t b[2]) {
    asm volatile("mma.sync.aligned.m16n8k16.row.col.f32.f16.f16.f32 "
                 "{%0,%1,%2,%3}, {%4,%5,%6,%7}, {%8,%9}, {%0,%1,%2,%3};"
                 : "+f"(c[0]), "+f"(c[1]), "+f"(c[2]), "+f"(c[3])
                 : "r"(a[0]), "r"(a[1]), "r"(a[2]), "r"(a[3]), "r"(b[0]), "r"(b[1]));
}

// =================================================================
// wprep: transpose weights to fp16 [col][k] for MMA B operands
// =================================================================
__global__ __launch_bounds__(256) void wprep(
    const float* __restrict__ Wf, const float* __restrict__ Wg,
    const float* __restrict__ Wh, const float* __restrict__ Wv)
{
    const int stride = gridDim.x * 256;
    for (int i = blockIdx.x * 256 + threadIdx.x; i < 3*FF*CC; i += stride) {
        int o = i / (FF*CC);
        int rem = i - o * (FF*CC);
        int c = rem >> 8;          // col 0..127
        int k = rem & 255;         // k 0..255
        const float* W = (o == 0) ? Wf : (o == 1) ? Wg : Wh;
        g_Wt[i] = __float2half(W[k * FF + c]);
    }
    for (int i = blockIdx.x * 256 + threadIdx.x; i < FF*FF; i += stride) {
        int c = i >> 7, k = i & 127;
        g_Wvt[i] = __float2half(Wv[k * FF + c]);
    }
}

// =================================================================
// proj_mma: fused 3-way projection via fp16 HMMA.
// CTA = 64 rows x 128 cols, all 3 outputs share x tile.
// x fp32 -> fp16 smem (all K=256), W chunks double-buffered cp.async.
// grid = 256 CTAs, 256 threads (8 warps: 2x4, warp tile 32x32).
// =================================================================
// smem: XS 4 chunks [64][72]h = 36864 ; W bufs 2 x (3 x [128][72]h) = 110592
#define PJ_XS    0
#define PJ_XCH   9216          // 64*144
#define PJ_W     36864
#define PJ_WBUF  55296         // 3*18432
#define PJ_WO    18432         // 128*144
#define PJ_SMEM  147456

__global__ __launch_bounds__(256, 1) void proj_mma(
    const float* __restrict__ x,
    const float* __restrict__ bf, const float* __restrict__ bg,
    const float* __restrict__ bh)
{
    extern __shared__ char smem[];
    const uint32_t sb = smem_to_u32(smem);
    const int tid  = threadIdx.x;
    const int lane = tid & 31, wid = tid >> 5;
    const int R0 = (wid >> 2) * 32;   // row offset within 64
    const int C0 = (wid & 3) * 32;    // col offset within 128
    const int row0 = blockIdx.x * 64;

    // issue W chunks 0,1 via cp.async
    #pragma unroll
    for (int c = 0; c < 2; c++) {
        uint32_t bufb = sb + PJ_W + (uint32_t)c * PJ_WBUF;
        #pragma unroll
        for (int o = 0; o < 3; o++) {
            const __half* src0 = g_Wt + o * (FF*CC);
            #pragma unroll
            for (int e = tid; e < 1024; e += 256) {
                int col = e >> 3, seg = e & 7;
                CP_ASYNC16(bufb + (uint32_t)(o*PJ_WO + col*144 + seg*16),
                           src0 + col*CC + c*64 + seg*8);
            }
        }
        CP_COMMIT();
    }

    // convert x tile [64][256] fp32 -> fp16 smem (chunked layout)
    for (int e = tid; e < 4096; e += 256) {
        int r = e >> 6, seg = e & 63;
        int k = seg * 4;
        float4 v = *(const float4*)&x[(size_t)(row0 + r) * CC + k];
        __half h4[4] = { __float2half(v.x), __float2half(v.y),
                         __float2half(v.z), __float2half(v.w) };
        uint32_t off = PJ_XS + (uint32_t)(k >> 6) * PJ_XCH + r*144 + (k & 63)*2;
        *(uint2*)(smem + off) = *(const uint2*)h4;
    }
    __syncthreads();

    float acc[3][2][4][4];
    #pragma unroll
    for (int o = 0; o < 3; o++)
        #pragma unroll
        for (int mi = 0; mi < 2; mi++)
            #pragma unroll
            for (int ni = 0; ni < 4; ni++)
                #pragma unroll
                for (int q = 0; q < 4; q++) acc[o][mi][ni][q] = 0.f;

    const int arow  = R0 + (lane & 15);
    const int acolB = ((lane >> 4) << 3);
    const int l15   = lane & 15;
    const int brow  = C0 + (l15 & 7);
    const int bcolB = ((l15 >> 3) << 3);

    for (int c = 0; c < 4; c++) {
        if (c < 3) { CP_WAIT(1); } else { CP_WAIT(0); }
        __syncthreads();
        const uint32_t xb = sb + PJ_XS + (uint32_t)c * PJ_XCH;
        const uint32_t wb = sb + PJ_W + (uint32_t)(c & 1) * PJ_WBUF;
        #pragma unroll
        for (int ks = 0; ks < 4; ks++) {
            const int k0 = ks * 16;
            uint32_t aH[2][4];
            #pragma unroll
            for (int mi = 0; mi < 2; mi++) {
                uint32_t ad = xb + (uint32_t)(((arow + mi*16)*72 + k0 + acolB) * 2);
                ldsm_x4(aH[mi][0], aH[mi][1], aH[mi][2], aH[mi][3], ad);
            }
            #pragma unroll
            for (int o = 0; o < 3; o++) {
                uint32_t bH[4][2];
                #pragma unroll
                for (int ni = 0; ni < 4; ni++) {
                    uint32_t bd = wb + (uint32_t)(o*PJ_WO + ((brow + ni*8)*72 + k0 + bcolB) * 2);
                    ldsm_x2(bH[ni][0], bH[ni][1], bd);
                }
                #pragma unroll
                for (int mi = 0; mi < 2; mi++)
                    #pragma unroll
                    for (int ni = 0; ni < 4; ni++)
                        mma_f16(acc[o][mi][ni], aH[mi], bH[ni]);
            }
        }
        __syncthreads();
        if (c + 2 < 4) {
            uint32_t bufb = sb + PJ_W + (uint32_t)(c & 1) * PJ_WBUF;
            #pragma unroll
            for (int o = 0; o < 3; o++) {
                const __half* src0 = g_Wt + o * (FF*CC);
                #pragma unroll
                for (int e = tid; e < 1024; e += 256) {
                    int col = e >> 3, seg = e & 7;
                    CP_ASYNC16(bufb + (uint32_t)(o*PJ_WO + col*144 + seg*16),
                               src0 + col*CC + (c+2)*64 + seg*8);
                }
            }
            CP_COMMIT();
        }
    }

    // epilogue: add bias, store fx/gx fp16, hx fp32
    #pragma unroll
    for (int mi = 0; mi < 2; mi++)
        #pragma unroll
        for (int ni = 0; ni < 4; ni++) {
            int r0q = row0 + R0 + mi*16 + (lane >> 2);
            int col = C0 + ni*8 + 2*(lane & 3);
            float bfc0 = bf[col], bfc1 = bf[col+1];
            float bgc0 = bg[col], bgc1 = bg[col+1];
            float bhc0 = bh[col], bhc1 = bh[col+1];
            #pragma unroll
            for (int h = 0; h < 2; h++) {
                int r = r0q + h*8;
                size_t o = (size_t)r * FF + col;
                __half2 vf = { __float2half(acc[0][mi][ni][h*2+0] + bfc0),
                               __float2half(acc[0][mi][ni][h*2+1] + bfc1) };
                __half2 vg = { __float2half(acc[1][mi][ni][h*2+0] + bgc0),
                               __float2half(acc[1][mi][ni][h*2+1] + bgc1) };
                float2 vh = { acc[2][mi][ni][h*2+0] + bhc0,
                              acc[2][mi][ni][h*2+1] + bhc1 };
                *(__half2*)&g_fx16[o] = vf;
                *(__half2*)&g_gx16[o] = vg;
                *(float2*)&g_hx[o]    = vh;
            }
        }
}

// =================================================================
// score_mma: S tile = fx @ gx^T, single fp16 chain, 256 threads,
// 8 warps 64x32 tiles, both K-chunks prefetched (double buffer).
// grid (jt=16, it=16, b=8). (measured-good R11 version)
// =================================================================
#define S2_A  0
#define S2_B  18432        // 128*72*2
#define S2_CH 36864
#define SC_SMEM (2*S2_CH + 512)

__global__ __launch_bounds__(256, 1) void score_mma()
{
    extern __shared__ char smem[];
    const uint32_t sb = smem_to_u32(smem);
    const int tid  = threadIdx.x;
    const int lane = tid & 31, wid = tid >> 5;
    const int wrow = wid >> 2, wcol = wid & 3;
    const int R0 = wrow * 64, C0 = wcol * 32;
    const int b = blockIdx.z, it = blockIdx.y, jt = blockIdx.x;
    const int row0 = it * 128, col0 = jt * 128;

    const __half* fx = g_fx16 + (size_t)(b*NN + row0) * FF;
    const __half* gx = g_gx16 + (size_t)(b*NN + col0) * FF;

    #pragma unroll
    for (int c = 0; c < 2; c++) {
        uint32_t bufb = sb + c * S2_CH;
        #pragma unroll
        for (int e = tid; e < 1024; e += 256) {
            int r = e >> 3, s = e & 7;
            uint32_t d = bufb + (uint32_t)(r*144 + s*16);
            size_t go = (size_t)r * FF + c*64 + s*8;
            CP_ASYNC16(d + S2_A, fx + go);
            CP_ASYNC16(d + S2_B, gx + go);
        }
        CP_COMMIT();
    }

    float acc[4][4][4];
    #pragma unroll
    for (int mi = 0; mi < 4; mi++)
        #pragma unroll
        for (int ni = 0; ni < 4; ni++)
            #pragma unroll
            for (int q = 0; q < 4; q++) acc[mi][ni][q] = 0.f;

    const int arow  = R0 + (lane & 15);
    const int acolB = ((lane >> 4) << 3);
    const int l15   = lane & 15;
    const int brow  = C0 + (l15 & 7);
    const int bcolB = ((l15 >> 3) << 3);

    #pragma unroll
    for (int c = 0; c < 2; c++) {
        if (c == 0) { CP_WAIT(1); } else { CP_WAIT(0); }
        __syncthreads();
        uint32_t bufb = sb + (uint32_t)c * S2_CH;
        #pragma unroll
        for (int ks = 0; ks < 4; ks++) {
            const int k0 = ks * 16;
            uint32_t aH[4][4], bH[4][2];
            #pragma unroll
            for (int mi = 0; mi < 4; mi++) {
                uint32_t ad = bufb + S2_A + (uint32_t)(((arow + mi*16)*72 + k0 + acolB) * 2);
                ldsm_x4(aH[mi][0], aH[mi][1], aH[mi][2], aH[mi][3], ad);
            }
            #pragma unroll
            for (int ni = 0; ni < 4; ni++) {
                uint32_t bd = bufb + S2_B + (uint32_t)(((brow + ni*8)*72 + k0 + bcolB) * 2);
                ldsm_x2(bH[ni][0], bH[ni][1], bd);
            }
            #pragma unroll
            for (int mi = 0; mi < 4; mi++)
                #pragma unroll
                for (int ni = 0; ni < 4; ni++)
                    mma_f16(acc[mi][ni], aH[mi], bH[ni]);
        }
        __syncthreads();
    }

    float* red = (float*)(smem + 2*S2_CH);
    if (tid < 128) red[tid] = 0.f;
    __syncthreads();

    #pragma unroll
    for (int mi = 0; mi < 4; mi++) {
        float s0 = 0.f, s1 = 0.f;
        #pragma unroll
        for (int ni = 0; ni < 4; ni++) {
            acc[mi][ni][0] = __expf(acc[mi][ni][0]);
            acc[mi][ni][1] = __expf(acc[mi][ni][1]);
            acc[mi][ni][2] = __expf(acc[mi][ni][2]);
            acc[mi][ni][3] = __expf(acc[mi][ni][3]);
            s0 += acc[mi][ni][0] + acc[mi][ni][1];
            s1 += acc[mi][ni][2] + acc[mi][ni][3];
        }
        s0 += __shfl_xor_sync(0xffffffffu, s0, 1);
        s0 += __shfl_xor_sync(0xffffffffu, s0, 2);
        s1 += __shfl_xor_sync(0xffffffffu, s1, 1);
        s1 += __shfl_xor_sync(0xffffffffu, s1, 2);
        if ((lane & 3) == 0) {
            int r = R0 + mi*16 + (lane >> 2);
            atomicAdd(&red[r], s0);
            atomicAdd(&red[r + 8], s1);
        }
    }
    __syncthreads();
    if (tid < 128)
        g_spart[((size_t)(b*NN) + row0 + tid) * 16 + jt] = red[tid];

    __half* stage = (__half*)smem;
    #pragma unroll
    for (int mi = 0; mi < 4; mi++)
        #pragma unroll
        for (int ni = 0; ni < 4; ni++)
            #pragma unroll
            for (int q = 0; q < 4; q++) {
                int i = R0 + mi*16 + (lane >> 2) + ((q >> 1) << 3);
                int j = C0 + ni*8 + 2*(lane & 3) + (q & 1);
                stage[j*136 + i] = __float2half(acc[mi][ni][q]);
            }
    __syncthreads();
    {
        int j = tid >> 1, half = tid & 1;
        uint4* dst = (uint4*)(g_eT + ((size_t)(b*NN + col0 + j))*NN + row0 + half*64);
        const uint4* src = (const uint4*)(stage + j*136 + half*64);
        #pragma unroll
        for (int i = 0; i < 8; i++) dst[i] = src[i];
    }
}

// =================================================================
// hxT_kernel: hxT[b][f][n] = fp16( hx[b][n][f]/rowsum[n] * 2^14 )
// =================================================================
__global__ __launch_bounds__(256) void hxT_kernel()
{
    __shared__ __half stage[128][136];
    __shared__ float inv[128];
    const int b = blockIdx.y, n0 = blockIdx.x * 128, t = threadIdx.x;

    if (t < 128) {
        const float* p = &g_spart[((size_t)(b*NN) + n0 + t) * 16];
        float s = 0.f;
        #pragma unroll
        for (int i = 0; i < 16; i++) s += p[i];
        inv[t] = HXT_SCALE / s;
    }
    __syncthreads();

    const float* hx = g_hx + ((size_t)(b*NN + n0)) * FF;

    for (int e = t; e < 16384; e += 256) {
        int n = e >> 7, f = e & 127;
        stage[f][n] = __float2half(hx[e] * inv[n]);
    }
    __syncthreads();
    {
        int f = t >> 1, h = t & 1;
        uint4* dst = (uint4*)(g_hxT + ((size_t)(b*FF) + f) * NN + n0 + h*64);
        const uint4* src = (const uint4*)&stage[f][h*64];
        #pragma unroll
        for (int i = 0; i < 8; i++) dst[i] = src[i];
    }
}

// =================================================================
// out_mma: O[b][f][m] = (sum_n hxT[f][n]*eT[m][n]) * 2^-14
// CTA 128(f) x 64(m), K=2048 in 32 chunks, 3-stage cp.async, 2 CTAs/SM.
// single fp16 chain. grid (mt=32, b=8), 256 threads. (measured-good)
// =================================================================
#define O_A  0             // 128*72*2 = 18432
#define O_B  18432         // 64*72*2 = 9216
#define O_CH 27648
#define OT_SMEM (3*O_CH)   // 82944

__global__ __launch_bounds__(256, 2) void out_mma()
{
    extern __shared__ char smem[];
    const uint32_t sb = smem_to_u32(smem);
    const int tid  = threadIdx.x;
    const int lane = tid & 31, wid = tid >> 5;
    const int wrow = wid >> 2, wcol = wid & 3;
    const int R0 = wrow * 64;       // f offset within 128
    const int C0 = wcol * 16;       // m offset within 64
    const int b = blockIdx.y, m0 = blockIdx.x * 64;

    const __half* Ah = g_hxT + (size_t)b * FF * NN;
    const __half* Bm = g_eT + (size_t)b * NN * NN + (size_t)m0 * NN;

    auto fill = [&](int buf, int kc) {
        uint32_t bufb = sb + (uint32_t)buf * O_CH;
        #pragma unroll
        for (int e = tid; e < 1024; e += 256) {
            int r = e >> 3, s = e & 7;
            size_t go = (size_t)r * NN + (size_t)kc*64 + s*8;
            CP_ASYNC16(bufb + O_A + (uint32_t)(r*144 + s*16), Ah + go);
        }
        #pragma unroll
        for (int e = tid; e < 512; e += 256) {
            int r = e >> 3, s = e & 7;
            size_t go = (size_t)r * NN + (size_t)kc*64 + s*8;
            CP_ASYNC16(bufb + O_B + (uint32_t)(r*144 + s*16), Bm + go);
        }
        CP_COMMIT();
    };

    float acc[4][2][4];
    #pragma unroll
    for (int mi = 0; mi < 4; mi++)
        #pragma unroll
        for (int ni = 0; ni < 2; ni++)
            #pragma unroll
            for (int q = 0; q < 4; q++) acc[mi][ni][q] = 0.f;

    fill(0, 0);
    fill(1, 1);
    fill(2, 2);

    const int arow  = R0 + (lane & 15);
    const int acolB = ((lane >> 4) << 3);
    const int bn    = C0 + ((lane >> 4) << 3) + (lane & 7);
    const int bk    = ((lane >> 3) & 1) << 3;

    for (int kc = 0; kc < 32; kc++) {
        if (kc == 31)      { CP_WAIT(0); }
        else if (kc == 30) { CP_WAIT(1); }
        else               { CP_WAIT(2); }
        __syncthreads();
        uint32_t bufb = sb + (uint32_t)(kc % 3) * O_CH;
        #pragma unroll
        for (int ks = 0; ks < 4; ks++) {
            const int k0 = ks * 16;
            uint32_t aH[4][4], bb[4];
            #pragma unroll
            for (int mi = 0; mi < 4; mi++) {
                uint32_t ad = bufb + O_A + (uint32_t)(((arow + mi*16)*72 + k0 + acolB) * 2);
                ldsm_x4(aH[mi][0], aH[mi][1], aH[mi][2], aH[mi][3], ad);
            }
            {
                uint32_t bd = bufb + O_B + (uint32_t)((bn*72 + k0 + bk) * 2);
                ldsm_x4(bb[0], bb[1], bb[2], bb[3], bd);
            }
            #pragma unroll
            for (int mi = 0; mi < 4; mi++) {
                mma_f16(acc[mi][0], aH[mi], &bb[0]);
                mma_f16(acc[mi][1], aH[mi], &bb[2]);
            }
        }
        __syncthreads();
        if (kc + 3 < 32) fill(kc % 3, kc + 3);
    }

    #pragma unroll
    for (int mi = 0; mi < 4; mi++)
        #pragma unroll
        for (int ni = 0; ni < 2; ni++) {
            int f = R0 + mi*16 + (lane >> 2);
            int m = m0 + C0 + ni*8 + 2*(lane & 3);
            float2 v0 = { acc[mi][ni][0]*HXT_INV_SCALE, acc[mi][ni][1]*HXT_INV_SCALE };
            float2 v1 = { acc[mi][ni][2]*HXT_INV_SCALE, acc[mi][ni][3]*HXT_INV_SCALE };
            *(float2*)&g_O[((size_t)(b*FF) + f    ) * NN + m] = v0;
            *(float2*)&g_O[((size_t)(b*FF) + f + 8) * NN + m] = v1;
        }
}

// =================================================================
// final_mma: out = g_O(flat [16384][128]) @ Wv + bv, fp16 HMMA.
// CTA 64 rows x 128 cols, K=128 single-shot. grid 256.
// =================================================================
#define FN_XS   0              // 2 chunks [64][72]h = 18432
#define FN_XCH  9216
#define FN_W    18432          // 2 chunks [128][72]h = 36864
#define FN_WCH  18432
#define FN_SMEM 55296

__global__ __launch_bounds__(256) void final_mma(
    const float* __restrict__ bv, float* __restrict__ out)
{
    extern __shared__ char smem[];
    const uint32_t sb = smem_to_u32(smem);
    const int tid  = threadIdx.x;
    const int lane = tid & 31, wid = tid >> 5;
    const int R0 = (wid >> 2) * 32;
    const int C0 = (wid & 3) * 32;
    const int row0 = blockIdx.x * 64;

    // cp.async Wv (both chunks)
    #pragma unroll
    for (int c = 0; c < 2; c++) {
        #pragma unroll
        for (int e = tid; e < 1024; e += 256) {
            int col = e >> 3, seg = e & 7;
            CP_ASYNC16(sb + FN_W + (uint32_t)(c*FN_WCH + col*144 + seg*16),
                       g_Wvt + col*FF + c*64 + seg*8);
        }
    }
    CP_COMMIT();

    // convert A tile from g_O fp32
    const float* A = (const float*)g_O;
    for (int e = tid; e < 2048; e += 256) {
        int r = e >> 5, seg = e & 31;
        int k = seg * 4;
        float4 v = *(const float4*)&A[(size_t)(row0 + r) * FF + k];
        __half h4[4] = { __float2half(v.x), __float2half(v.y),
                         __float2half(v.z), __float2half(v.w) };
        uint32_t off = FN_XS + (uint32_t)(k >> 6) * FN_XCH + r*144 + (k & 63)*2;
        *(uint2*)(smem + off) = *(const uint2*)h4;
    }
    CP_WAIT(0);
    __syncthreads();

    float acc[2][4][4];
    #pragma unroll
    for (int mi = 0; mi < 2; mi++)
        #pragma unroll
        for (int ni = 0; ni < 4; ni++)
            #pragma unroll
            for (int q = 0; q < 4; q++) acc[mi][ni][q] = 0.f;

    const int arow  = R0 + (lane & 15);
    const int acolB = ((lane >> 4) << 3);
    const int l15   = lane & 15;
    const int brow  = C0 + (l15 & 7);
    const int bcolB = ((l15 >> 3) << 3);

    #pragma unroll
    for (int c = 0; c < 2; c++) {
        const uint32_t xb = sb + FN_XS + (uint32_t)c * FN_XCH;
        const uint32_t wb = sb + FN_W  + (uint32_t)c * FN_WCH;
        #pragma unroll
        for (int ks = 0; ks < 4; ks++) {
            const int k0 = ks * 16;
            uint32_t aH[2][4], bH[4][2];
            #pragma unroll
            for (int mi = 0; mi < 2; mi++) {
                uint32_t ad = xb + (uint32_t)(((arow + mi*16)*72 + k0 + acolB) * 2);
                ldsm_x4(aH[mi][0], aH[mi][1], aH[mi][2], aH[mi][3], ad);
            }
            #pragma unroll
            for (int ni = 0; ni < 4; ni++) {
                uint32_t bd = wb + (uint32_t)(((brow + ni*8)*72 + k0 + bcolB) * 2);
                ldsm_x2(bH[ni][0], bH[ni][1], bd);
            }
            #pragma unroll
            for (int mi = 0; mi < 2; mi++)
                #pragma unroll
                for (int ni = 0; ni < 4; ni++)
                    mma_f16(acc[mi][ni], aH[mi], bH[ni]);
        }
    }

    #pragma unroll
    for (int mi = 0; mi < 2; mi++)
        #pragma unroll
        for (int ni = 0; ni < 4; ni++) {
            int r0q = row0 + R0 + mi*16 + (lane >> 2);
            int col = C0 + ni*8 + 2*(lane & 3);
            float b0 = bv[col], b1 = bv[col+1];
            #pragma unroll
            for (int h = 0; h < 2; h++) {
                int r = r0q + h*8;
                float2 v = { acc[mi][ni][h*2+0] + b0, acc[mi][ni][h*2+1] + b1 };
                *(float2*)&out[(size_t)r * FF + col] = v;
            }
        }
}

// =================================================================
extern "C" void kernel_launch(void* const* d_in, const int* in_sizes, int n_in,
                              void* d_out, int out_size)
{
    const float* x  = (const float*)d_in[0];
    const float* Wf = (const float*)d_in[1];
    const float* bf = (const float*)d_in[2];
    const float* Wg = (const float*)d_in[3];
    const float* bg = (const float*)d_in[4];
    const float* Wh = (const float*)d_in[5];
    const float* bh = (const float*)d_in[6];
    const float* Wv = (const float*)d_in[7];
    const float* bv = (const float*)d_in[8];
    float* out = (float*)d_out;

    cudaFuncSetAttribute(proj_mma,  cudaFuncAttributeMaxDynamicSharedMemorySize, PJ_SMEM);
    cudaFuncSetAttribute(score_mma, cudaFuncAttributeMaxDynamicSharedMemorySize, SC_SMEM);
    cudaFuncSetAttribute(out_mma,   cudaFuncAttributeMaxDynamicSharedMemorySize, OT_SMEM);
    cudaFuncSetAttribute(final_mma, cudaFuncAttributeMaxDynamicSharedMemorySize, FN_SMEM);

    // weight transpose + fp16 conversion
    wprep<<<128, 256>>>(Wf, Wg, Wh, Wv);

    // fused projections via HMMA: fx/gx -> fp16, hx -> fp32
    proj_mma<<<MTOT/64, 256, PJ_SMEM>>>(x, bf, bg, bh);

    // scores + exp + transposed fp16 store + partial row sums
    score_mma<<<dim3(16, 16, 8), 256, SC_SMEM>>>();

    // hxT = hx / rowsum * 2^14, transposed, fp16
    hxT_kernel<<<dim3(16, 8), 256>>>();

    // O = hxT @ eT^T * 2^-14
    out_mma<<<dim3(32, 8), 256, OT_SMEM>>>();

    // final: reshape([B,F,N] flat as [B,N,F]) @ Wv + bv via HMMA
    final_mma<<<MTOT/64, 256, FN_SMEM>>>(bv, out);
}

// round 14
// speedup vs baseline: 2.7743x; 1.0596x over previous
#include <cuda_runtime.h>
#include <cuda_bf16.h>
#include <cuda_fp16.h>
#include <cstdint>

#define BB 8
#define NN 2048
#define CC 256
#define FF 128
#define MTOT (BB*NN)   // 16384

// ---------------- scratch (no cudaMalloc allowed) ----------------
__device__ __half        g_fx16[MTOT*FF];          // 4 MB
__device__ __half        g_gx16[MTOT*FF];          // 4 MB
__device__ float         g_hx [MTOT*FF];           // 8 MB
__device__ __half        g_hxT[(size_t)BB*FF*NN];  // [b][f][n] fp16 (scaled)
__device__ __half        g_eT[(size_t)BB*NN*NN];   // [b][m][n] fp16, 64 MB
__device__ float         g_spart[(size_t)BB*NN*16];// partial row sums
__device__ float         g_O [MTOT*FF];            // [b][f][m] 8 MB
__device__ __half        g_Wt[3*FF*CC];            // Wf/Wg/Wh transposed fp16 [o][col][k]
__device__ __half        g_Wvt[FF*FF];             // Wv transposed fp16 [col][k]

#define HXT_SCALE 16384.0f
#define HXT_INV_SCALE (1.0f/16384.0f)

// ======================= PTX helpers =======================
__device__ __forceinline__ uint32_t smem_to_u32(const void* p) {
    uint32_t a;
    asm("{ .reg .u64 t; cvta.to.shared.u64 t, %1; cvt.u32.u64 %0, t; }" : "=r"(a) : "l"(p));
    return a;
}
#define CP_ASYNC16(dst, src) \
    asm volatile("cp.async.cg.shared.global [%0], [%1], 16;" :: "r"(dst), "l"(src) : "memory")
#define CP_COMMIT() asm volatile("cp.async.commit_group;" ::: "memory")
#define CP_WAIT(n)  asm volatile("cp.async.wait_group %0;" :: "n"(n) : "memory")

__device__ __forceinline__ void ldsm_x4(uint32_t& r0, uint32_t& r1, uint32_t& r2, uint32_t& r3, uint32_t a) {
    asm volatile("ldmatrix.sync.aligned.m8n8.x4.shared.b16 {%0,%1,%2,%3}, [%4];"
                 : "=r"(r0), "=r"(r1), "=r"(r2), "=r"(r3) : "r"(a));
}
__device__ __forceinline__ void ldsm_x2(uint32_t& r0, uint32_t& r1, uint32_t a) {
    asm volatile("ldmatrix.sync.aligned.m8n8.x2.shared.b16 {%0,%1}, [%2];"
                 : "=r"(r0), "=r"(r1) : "r"(a));
}
__device__ __forceinline__ void mma_f16(float c[4], const uint32_t a[4], const uint32_t b[2]) {
    asm volatile("mma.sync.aligned.m16n8k16.row.col.f32.f16.f16.f32 "
                 "{%0,%1,%2,%3}, {%4,%5,%6,%7}, {%8,%9}, {%0,%1,%2,%3};"
                 : "+f"(c[0]), "+f"(c[1]), "+f"(c[2]), "+f"(c[3])
                 : "r"(a[0]), "r"(a[1]), "r"(a[2]), "r"(a[3]), "r"(b[0]), "r"(b[1]));
}

// =================================================================
// wprep: transpose weights to fp16 [col][k] for MMA B operands
// =================================================================
__global__ __launch_bounds__(256) void wprep(
    const float* __restrict__ Wf, const float* __restrict__ Wg,
    const float* __restrict__ Wh, const float* __restrict__ Wv)
{
    const int stride = gridDim.x * 256;
    for (int i = blockIdx.x * 256 + threadIdx.x; i < 3*FF*CC; i += stride) {
        int o = i / (FF*CC);
        int rem = i - o * (FF*CC);
        int c = rem >> 8;          // col 0..127
        int k = rem & 255;         // k 0..255
        const float* W = (o == 0) ? Wf : (o == 1) ? Wg : Wh;
        g_Wt[i] = __float2half(W[k * FF + c]);
    }
    for (int i = blockIdx.x * 256 + threadIdx.x; i < FF*FF; i += stride) {
        int c = i >> 7, k = i & 127;
        g_Wvt[i] = __float2half(Wv[k * FF + c]);
    }
}

// =================================================================
// proj_mma: fused 3-way projection via fp16 HMMA. (measured-good R13)
// =================================================================
#define PJ_XS    0
#define PJ_XCH   9216          // 64*144
#define PJ_W     36864
#define PJ_WBUF  55296         // 3*18432
#define PJ_WO    18432         // 128*144
#define PJ_SMEM  147456

__global__ __launch_bounds__(256, 1) void proj_mma(
    const float* __restrict__ x,
    const float* __restrict__ bf, const float* __restrict__ bg,
    const float* __restrict__ bh)
{
    extern __shared__ char smem[];
    const uint32_t sb = smem_to_u32(smem);
    const int tid  = threadIdx.x;
    const int lane = tid & 31, wid = tid >> 5;
    const int R0 = (wid >> 2) * 32;
    const int C0 = (wid & 3) * 32;
    const int row0 = blockIdx.x * 64;

    #pragma unroll
    for (int c = 0; c < 2; c++) {
        uint32_t bufb = sb + PJ_W + (uint32_t)c * PJ_WBUF;
        #pragma unroll
        for (int o = 0; o < 3; o++) {
            const __half* src0 = g_Wt + o * (FF*CC);
            #pragma unroll
            for (int e = tid; e < 1024; e += 256) {
                int col = e >> 3, seg = e & 7;
                CP_ASYNC16(bufb + (uint32_t)(o*PJ_WO + col*144 + seg*16),
                           src0 + col*CC + c*64 + seg*8);
            }
        }
        CP_COMMIT();
    }

    for (int e = tid; e < 4096; e += 256) {
        int r = e >> 6, seg = e & 63;
        int k = seg * 4;
        float4 v = *(const float4*)&x[(size_t)(row0 + r) * CC + k];
        __half h4[4] = { __float2half(v.x), __float2half(v.y),
                         __float2half(v.z), __float2half(v.w) };
        uint32_t off = PJ_XS + (uint32_t)(k >> 6) * PJ_XCH + r*144 + (k & 63)*2;
        *(uint2*)(smem + off) = *(const uint2*)h4;
    }
    __syncthreads();

    float acc[3][2][4][4];
    #pragma unroll
    for (int o = 0; o < 3; o++)
        #pragma unroll
        for (int mi = 0; mi < 2; mi++)
            #pragma unroll
            for (int ni = 0; ni < 4; ni++)
                #pragma unroll
                for (int q = 0; q < 4; q++) acc[o][mi][ni][q] = 0.f;

    const int arow  = R0 + (lane & 15);
    const int acolB = ((lane >> 4) << 3);
    const int l15   = lane & 15;
    const int brow  = C0 + (l15 & 7);
    const int bcolB = ((l15 >> 3) << 3);

    for (int c = 0; c < 4; c++) {
        if (c < 3) { CP_WAIT(1); } else { CP_WAIT(0); }
        __syncthreads();
        const uint32_t xb = sb + PJ_XS + (uint32_t)c * PJ_XCH;
        const uint32_t wb = sb + PJ_W + (uint32_t)(c & 1) * PJ_WBUF;
        #pragma unroll
        for (int ks = 0; ks < 4; ks++) {
            const int k0 = ks * 16;
            uint32_t aH[2][4];
            #pragma unroll
            for (int mi = 0; mi < 2; mi++) {
                uint32_t ad = xb + (uint32_t)(((arow + mi*16)*72 + k0 + acolB) * 2);
                ldsm_x4(aH[mi][0], aH[mi][1], aH[mi][2], aH[mi][3], ad);
            }
            #pragma unroll
            for (int o = 0; o < 3; o++) {
                uint32_t bH[4][2];
                #pragma unroll
                for (int ni = 0; ni < 4; ni++) {
                    uint32_t bd = wb + (uint32_t)(o*PJ_WO + ((brow + ni*8)*72 + k0 + bcolB) * 2);
                    ldsm_x2(bH[ni][0], bH[ni][1], bd);
                }
                #pragma unroll
                for (int mi = 0; mi < 2; mi++)
                    #pragma unroll
                    for (int ni = 0; ni < 4; ni++)
                        mma_f16(acc[o][mi][ni], aH[mi], bH[ni]);
            }
        }
        __syncthreads();
        if (c + 2 < 4) {
            uint32_t bufb = sb + PJ_W + (uint32_t)(c & 1) * PJ_WBUF;
            #pragma unroll
            for (int o = 0; o < 3; o++) {
                const __half* src0 = g_Wt + o * (FF*CC);
                #pragma unroll
                for (int e = tid; e < 1024; e += 256) {
                    int col = e >> 3, seg = e & 7;
                    CP_ASYNC16(bufb + (uint32_t)(o*PJ_WO + col*144 + seg*16),
                               src0 + col*CC + (c+2)*64 + seg*8);
                }
            }
            CP_COMMIT();
        }
    }

    #pragma unroll
    for (int mi = 0; mi < 2; mi++)
        #pragma unroll
        for (int ni = 0; ni < 4; ni++) {
            int r0q = row0 + R0 + mi*16 + (lane >> 2);
            int col = C0 + ni*8 + 2*(lane & 3);
            float bfc0 = bf[col], bfc1 = bf[col+1];
            float bgc0 = bg[col], bgc1 = bg[col+1];
            float bhc0 = bh[col], bhc1 = bh[col+1];
            #pragma unroll
            for (int h = 0; h < 2; h++) {
                int r = r0q + h*8;
                size_t o = (size_t)r * FF + col;
                __half2 vf = { __float2half(acc[0][mi][ni][h*2+0] + bfc0),
                               __float2half(acc[0][mi][ni][h*2+1] + bfc1) };
                __half2 vg = { __float2half(acc[1][mi][ni][h*2+0] + bgc0),
                               __float2half(acc[1][mi][ni][h*2+1] + bgc1) };
                float2 vh = { acc[2][mi][ni][h*2+0] + bhc0,
                              acc[2][mi][ni][h*2+1] + bhc1 };
                *(__half2*)&g_fx16[o] = vf;
                *(__half2*)&g_gx16[o] = vg;
                *(float2*)&g_hx[o]    = vh;
            }
        }
}

// =================================================================
// score_mma: (measured-good R11/R13 version, untouched)
// =================================================================
#define S2_A  0
#define S2_B  18432        // 128*72*2
#define S2_CH 36864
#define SC_SMEM (2*S2_CH + 512)

__global__ __launch_bounds__(256, 1) void score_mma()
{
    extern __shared__ char smem[];
    const uint32_t sb = smem_to_u32(smem);
    const int tid  = threadIdx.x;
    const int lane = tid & 31, wid = tid >> 5;
    const int wrow = wid >> 2, wcol = wid & 3;
    const int R0 = wrow * 64, C0 = wcol * 32;
    const int b = blockIdx.z, it = blockIdx.y, jt = blockIdx.x;
    const int row0 = it * 128, col0 = jt * 128;

    const __half* fx = g_fx16 + (size_t)(b*NN + row0) * FF;
    const __half* gx = g_gx16 + (size_t)(b*NN + col0) * FF;

    #pragma unroll
    for (int c = 0; c < 2; c++) {
        uint32_t bufb = sb + c * S2_CH;
        #pragma unroll
        for (int e = tid; e < 1024; e += 256) {
            int r = e >> 3, s = e & 7;
            uint32_t d = bufb + (uint32_t)(r*144 + s*16);
            size_t go = (size_t)r * FF + c*64 + s*8;
            CP_ASYNC16(d + S2_A, fx + go);
            CP_ASYNC16(d + S2_B, gx + go);
        }
        CP_COMMIT();
    }

    float acc[4][4][4];
    #pragma unroll
    for (int mi = 0; mi < 4; mi++)
        #pragma unroll
        for (int ni = 0; ni < 4; ni++)
            #pragma unroll
            for (int q = 0; q < 4; q++) acc[mi][ni][q] = 0.f;

    const int arow  = R0 + (lane & 15);
    const int acolB = ((lane >> 4) << 3);
    const int l15   = lane & 15;
    const int brow  = C0 + (l15 & 7);
    const int bcolB = ((l15 >> 3) << 3);

    #pragma unroll
    for (int c = 0; c < 2; c++) {
        if (c == 0) { CP_WAIT(1); } else { CP_WAIT(0); }
        __syncthreads();
        uint32_t bufb = sb + (uint32_t)c * S2_CH;
        #pragma unroll
        for (int ks = 0; ks < 4; ks++) {
            const int k0 = ks * 16;
            uint32_t aH[4][4], bH[4][2];
            #pragma unroll
            for (int mi = 0; mi < 4; mi++) {
                uint32_t ad = bufb + S2_A + (uint32_t)(((arow + mi*16)*72 + k0 + acolB) * 2);
                ldsm_x4(aH[mi][0], aH[mi][1], aH[mi][2], aH[mi][3], ad);
            }
            #pragma unroll
            for (int ni = 0; ni < 4; ni++) {
                uint32_t bd = bufb + S2_B + (uint32_t)(((brow + ni*8)*72 + k0 + bcolB) * 2);
                ldsm_x2(bH[ni][0], bH[ni][1], bd);
            }
            #pragma unroll
            for (int mi = 0; mi < 4; mi++)
                #pragma unroll
                for (int ni = 0; ni < 4; ni++)
                    mma_f16(acc[mi][ni], aH[mi], bH[ni]);
        }
        __syncthreads();
    }

    float* red = (float*)(smem + 2*S2_CH);
    if (tid < 128) red[tid] = 0.f;
    __syncthreads();

    #pragma unroll
    for (int mi = 0; mi < 4; mi++) {
        float s0 = 0.f, s1 = 0.f;
        #pragma unroll
        for (int ni = 0; ni < 4; ni++) {
            acc[mi][ni][0] = __expf(acc[mi][ni][0]);
            acc[mi][ni][1] = __expf(acc[mi][ni][1]);
            acc[mi][ni][2] = __expf(acc[mi][ni][2]);
            acc[mi][ni][3] = __expf(acc[mi][ni][3]);
            s0 += acc[mi][ni][0] + acc[mi][ni][1];
            s1 += acc[mi][ni][2] + acc[mi][ni][3];
        }
        s0 += __shfl_xor_sync(0xffffffffu, s0, 1);
        s0 += __shfl_xor_sync(0xffffffffu, s0, 2);
        s1 += __shfl_xor_sync(0xffffffffu, s1, 1);
        s1 += __shfl_xor_sync(0xffffffffu, s1, 2);
        if ((lane & 3) == 0) {
            int r = R0 + mi*16 + (lane >> 2);
            atomicAdd(&red[r], s0);
            atomicAdd(&red[r + 8], s1);
        }
    }
    __syncthreads();
    if (tid < 128)
        g_spart[((size_t)(b*NN) + row0 + tid) * 16 + jt] = red[tid];

    __half* stage = (__half*)smem;
    #pragma unroll
    for (int mi = 0; mi < 4; mi++)
        #pragma unroll
        for (int ni = 0; ni < 4; ni++)
            #pragma unroll
            for (int q = 0; q < 4; q++) {
                int i = R0 + mi*16 + (lane >> 2) + ((q >> 1) << 3);
                int j = C0 + ni*8 + 2*(lane & 3) + (q & 1);
                stage[j*136 + i] = __float2half(acc[mi][ni][q]);
            }
    __syncthreads();
    {
        int j = tid >> 1, half = tid & 1;
        uint4* dst = (uint4*)(g_eT + ((size_t)(b*NN + col0 + j))*NN + row0 + half*64);
        const uint4* src = (const uint4*)(stage + j*136 + half*64);
        #pragma unroll
        for (int i = 0; i < 8; i++) dst[i] = src[i];
    }
}

// =================================================================
// hxT_kernel: hxT[b][f][n] = fp16( hx[b][n][f]/rowsum[n] * 2^14 )
// REWORKED: 256 CTAs (64n x 128f tiles), float4 loads, more MLP.
// grid (32, 8), 256 threads.
// =================================================================
__global__ __launch_bounds__(256) void hxT_kernel()
{
    __shared__ __half stage[128][72];   // [f][n-local], pad 8
    __shared__ float inv[64];
    const int b = blockIdx.y, n0 = blockIdx.x * 64, t = threadIdx.x;

    if (t < 64) {
        const float* p = &g_spart[((size_t)(b*NN) + n0 + t) * 16];
        float s = 0.f;
        #pragma unroll
        for (int i = 0; i < 16; i++) s += p[i];
        inv[t] = HXT_SCALE / s;
    }
    __syncthreads();

    const float* hx = g_hx + ((size_t)(b*NN + n0)) * FF;

    // load 64 rows x 128 f as float4 (8 per thread), convert+scale, stage transposed
    #pragma unroll
    for (int idx = t; idx < 2048; idx += 256) {
        int r = idx >> 5;            // n-local 0..63
        int seg = idx & 31;          // f-group of 4
        float4 v = *(const float4*)&hx[(size_t)r * FF + seg*4];
        float s = inv[r];
        stage[seg*4+0][r] = __float2half(v.x * s);
        stage[seg*4+1][r] = __float2half(v.y * s);
        stage[seg*4+2][r] = __float2half(v.z * s);
        stage[seg*4+3][r] = __float2half(v.w * s);
    }
    __syncthreads();

    // store: 256 threads, f = t&127, part = t>>7 (2 parts x 32 n)
    {
        int f = t & 127, part = t >> 7;
        uint4* dst = (uint4*)(g_hxT + ((size_t)(b*FF) + f) * NN + n0 + part*32);
        const uint4* src = (const uint4*)&stage[f][part*32];
        #pragma unroll
        for (int i = 0; i < 4; i++) dst[i] = src[i];
    }
}

// =================================================================
// out_mma: O[b][f][m] = (sum_n hxT[f][n]*eT[m][n]) * 2^-14
// CTA 128(f) x 64(m), K=2048 in 32 chunks, 3-stage cp.async, 2 CTAs/SM.
// NEW: 4x2 warp layout (32f x 32m tiles) -> A dup 2, B dup 4 (-20% smem reads).
// grid (mt=32, b=8), 256 threads.
// =================================================================
#define O_A  0             // 128*72*2 = 18432
#define O_B  18432         // 64*72*2 = 9216
#define O_CH 27648
#define OT_SMEM (3*O_CH)   // 82944

__global__ __launch_bounds__(256, 2) void out_mma()
{
    extern __shared__ char smem[];
    const uint32_t sb = smem_to_u32(smem);
    const int tid  = threadIdx.x;
    const int lane = tid & 31, wid = tid >> 5;
    const int wrow = wid & 3;         // 4 f-groups
    const int wcol = wid >> 2;        // 2 m-groups
    const int R0 = wrow * 32;         // f offset within 128
    const int C0 = wcol * 32;         // m offset within 64
    const int b = blockIdx.y, m0 = blockIdx.x * 64;

    const __half* Ah = g_hxT + (size_t)b * FF * NN;
    const __half* Bm = g_eT + (size_t)b * NN * NN + (size_t)m0 * NN;

    auto fill = [&](int buf, int kc) {
        uint32_t bufb = sb + (uint32_t)buf * O_CH;
        #pragma unroll
        for (int e = tid; e < 1024; e += 256) {
            int r = e >> 3, s = e & 7;
            size_t go = (size_t)r * NN + (size_t)kc*64 + s*8;
            CP_ASYNC16(bufb + O_A + (uint32_t)(r*144 + s*16), Ah + go);
        }
        #pragma unroll
        for (int e = tid; e < 512; e += 256) {
            int r = e >> 3, s = e & 7;
            size_t go = (size_t)r * NN + (size_t)kc*64 + s*8;
            CP_ASYNC16(bufb + O_B + (uint32_t)(r*144 + s*16), Bm + go);
        }
        CP_COMMIT();
    };

    float acc[2][4][4];
    #pragma unroll
    for (int mi = 0; mi < 2; mi++)
        #pragma unroll
        for (int ni = 0; ni < 4; ni++)
            #pragma unroll
            for (int q = 0; q < 4; q++) acc[mi][ni][q] = 0.f;

    fill(0, 0);
    fill(1, 1);
    fill(2, 2);

    const int arow  = R0 + (lane & 15);
    const int acolB = ((lane >> 4) << 3);
    const int bn0   = C0 + ((lane >> 4) << 3) + (lane & 7);
    const int bk    = ((lane >> 3) & 1) << 3;

    for (int kc = 0; kc < 32; kc++) {
        if (kc == 31)      { CP_WAIT(0); }
        else if (kc == 30) { CP_WAIT(1); }
        else               { CP_WAIT(2); }
        __syncthreads();
        uint32_t bufb = sb + (uint32_t)(kc % 3) * O_CH;
        #pragma unroll
        for (int ks = 0; ks < 4; ks++) {
            const int k0 = ks * 16;
            uint32_t aH[2][4], bb[2][4];
            #pragma unroll
            for (int mi = 0; mi < 2; mi++) {
                uint32_t ad = bufb + O_A + (uint32_t)(((arow + mi*16)*72 + k0 + acolB) * 2);
                ldsm_x4(aH[mi][0], aH[mi][1], aH[mi][2], aH[mi][3], ad);
            }
            #pragma unroll
            for (int g = 0; g < 2; g++) {
                uint32_t bd = bufb + O_B + (uint32_t)(((bn0 + g*16)*72 + k0 + bk) * 2);
                ldsm_x4(bb[g][0], bb[g][1], bb[g][2], bb[g][3], bd);
            }
            #pragma unroll
            for (int mi = 0; mi < 2; mi++)
                #pragma unroll
                for (int g = 0; g < 2; g++) {
                    mma_f16(acc[mi][g*2+0], aH[mi], &bb[g][0]);
                    mma_f16(acc[mi][g*2+1], aH[mi], &bb[g][2]);
                }
        }
        __syncthreads();
        if (kc + 3 < 32) fill(kc % 3, kc + 3);
    }

    // epilogue: direct stores to g_O[b][f][m], scale 2^-14
    #pragma unroll
    for (int mi = 0; mi < 2; mi++)
        #pragma unroll
        for (int ni = 0; ni < 4; ni++) {
            int f = R0 + mi*16 + (lane >> 2);
            int m = m0 + C0 + ni*8 + 2*(lane & 3);
            float2 v0 = { acc[mi][ni][0]*HXT_INV_SCALE, acc[mi][ni][1]*HXT_INV_SCALE };
            float2 v1 = { acc[mi][ni][2]*HXT_INV_SCALE, acc[mi][ni][3]*HXT_INV_SCALE };
            *(float2*)&g_O[((size_t)(b*FF) + f    ) * NN + m] = v0;
            *(float2*)&g_O[((size_t)(b*FF) + f + 8) * NN + m] = v1;
        }
}

// =================================================================
// final_mma: out = g_O(flat [16384][128]) @ Wv + bv, fp16 HMMA.
// (measured-good R13 version, untouched)
// =================================================================
#define FN_XS   0
#define FN_XCH  9216
#define FN_W    18432
#define FN_WCH  18432
#define FN_SMEM 55296

__global__ __launch_bounds__(256) void final_mma(
    const float* __restrict__ bv, float* __restrict__ out)
{
    extern __shared__ char smem[];
    const uint32_t sb = smem_to_u32(smem);
    const int tid  = threadIdx.x;
    const int lane = tid & 31, wid = tid >> 5;
    const int R0 = (wid >> 2) * 32;
    const int C0 = (wid & 3) * 32;
    const int row0 = blockIdx.x * 64;

    #pragma unroll
    for (int c = 0; c < 2; c++) {
        #pragma unroll
        for (int e = tid; e < 1024; e += 256) {
            int col = e >> 3, seg = e & 7;
            CP_ASYNC16(sb + FN_W + (uint32_t)(c*FN_WCH + col*144 + seg*16),
                       g_Wvt + col*FF + c*64 + seg*8);
        }
    }
    CP_COMMIT();

    const float* A = (const float*)g_O;
    for (int e = tid; e < 2048; e += 256) {
        int r = e >> 5, seg = e & 31;
        int k = seg * 4;
        float4 v = *(const float4*)&A[(size_t)(row0 + r) * FF + k];
        __half h4[4] = { __float2half(v.x), __float2half(v.y),
                         __float2half(v.z), __float2half(v.w) };
        uint32_t off = FN_XS + (uint32_t)(k >> 6) * FN_XCH + r*144 + (k & 63)*2;
        *(uint2*)(smem + off) = *(const uint2*)h4;
    }
    CP_WAIT(0);
    __syncthreads();

    float acc[2][4][4];
    #pragma unroll
    for (int mi = 0; mi < 2; mi++)
        #pragma unroll
        for (int ni = 0; ni < 4; ni++)
            #pragma unroll
            for (int q = 0; q < 4; q++) acc[mi][ni][q] = 0.f;

    const int arow  = R0 + (lane & 15);
    const int acolB = ((lane >> 4) << 3);
    const int l15   = lane & 15;
    const int brow  = C0 + (l15 & 7);
    const int bcolB = ((l15 >> 3) << 3);

    #pragma unroll
    for (int c = 0; c < 2; c++) {
        const uint32_t xb = sb + FN_XS + (uint32_t)c * FN_XCH;
        const uint32_t wb = sb + FN_W  + (uint32_t)c * FN_WCH;
        #pragma unroll
        for (int ks = 0; ks < 4; ks++) {
            const int k0 = ks * 16;
            uint32_t aH[2][4], bH[4][2];
            #pragma unroll
            for (int mi = 0; mi < 2; mi++) {
                uint32_t ad = xb + (uint32_t)(((arow + mi*16)*72 + k0 + acolB) * 2);
                ldsm_x4(aH[mi][0], aH[mi][1], aH[mi][2], aH[mi][3], ad);
            }
            #pragma unroll
            for (int ni = 0; ni < 4; ni++) {
                uint32_t bd = wb + (uint32_t)(((brow + ni*8)*72 + k0 + bcolB) * 2);
                ldsm_x2(bH[ni][0], bH[ni][1], bd);
            }
            #pragma unroll
            for (int mi = 0; mi < 2; mi++)
                #pragma unroll
                for (int ni = 0; ni < 4; ni++)
                    mma_f16(acc[mi][ni], aH[mi], bH[ni]);
        }
    }

    #pragma unroll
    for (int mi = 0; mi < 2; mi++)
        #pragma unroll
        for (int ni = 0; ni < 4; ni++) {
            int r0q = row0 + R0 + mi*16 + (lane >> 2);
            int col = C0 + ni*8 + 2*(lane & 3);
            float b0 = bv[col], b1 = bv[col+1];
            #pragma unroll
            for (int h = 0; h < 2; h++) {
                int r = r0q + h*8;
                float2 v = { acc[mi][ni][h*2+0] + b0, acc[mi][ni][h*2+1] + b1 };
                *(float2*)&out[(size_t)r * FF + col] = v;
            }
        }
}

// =================================================================
extern "C" void kernel_launch(void* const* d_in, const int* in_sizes, int n_in,
                              void* d_out, int out_size)
{
    const float* x  = (const float*)d_in[0];
    const float* Wf = (const float*)d_in[1];
    const float* bf = (const float*)d_in[2];
    const float* Wg = (const float*)d_in[3];
    const float* bg = (const float*)d_in[4];
    const float* Wh = (const float*)d_in[5];
    const float* bh = (const float*)d_in[6];
    const float* Wv = (const float*)d_in[7];
    const float* bv = (const float*)d_in[8];
    float* out = (float*)d_out;

    cudaFuncSetAttribute(proj_mma,  cudaFuncAttributeMaxDynamicSharedMemorySize, PJ_SMEM);
    cudaFuncSetAttribute(score_mma, cudaFuncAttributeMaxDynamicSharedMemorySize, SC_SMEM);
    cudaFuncSetAttribute(out_mma,   cudaFuncAttributeMaxDynamicSharedMemorySize, OT_SMEM);
    cudaFuncSetAttribute(final_mma, cudaFuncAttributeMaxDynamicSharedMemorySize, FN_SMEM);

    // weight transpose + fp16 conversion
    wprep<<<128, 256>>>(Wf, Wg, Wh, Wv);

    // fused projections via HMMA: fx/gx -> fp16, hx -> fp32
    proj_mma<<<MTOT/64, 256, PJ_SMEM>>>(x, bf, bg, bh);

    // scores + exp + transposed fp16 store + partial row sums
    score_mma<<<dim3(16, 16, 8), 256, SC_SMEM>>>();

    // hxT = hx / rowsum * 2^14, transposed, fp16
    hxT_kernel<<<dim3(32, 8), 256>>>();

    // O = hxT @ eT^T * 2^-14
    out_mma<<<dim3(32, 8), 256, OT_SMEM>>>();

    // final: reshape([B,F,N] flat as [B,N,F]) @ Wv + bv via HMMA
    final_mma<<<MTOT/64, 256, FN_SMEM>>>(bv, out);
}